// round 6
// baseline (speedup 1.0000x reference)
#include <cuda_runtime.h>
#include <math.h>
#include <stdint.h>

#define B 4
#define S 2048
#define E 512
#define H 8
#define D 64
#define FF 2048
#define NTOK (B*S)

// ---- device scratch (static, allocation-free) ----
__device__ float g_V[(size_t)NTOK * E];     // [b,s,h,d] token-major, tf32-rounded
__device__ float g_Q[(size_t)B * H * S];    // [b,h,s]
__device__ float g_K[(size_t)B * H * S];    // [b,h,s]
__device__ float g_HO[(size_t)NTOK * E];    // head_out [b,s,e], tf32-rounded
__device__ float g_MID[(size_t)NTOK * FF];  // GELU(h@W1+b1), tf32-rounded
__device__ float g_Wt1[(size_t)FF * E];     // W1^T [N=FF][K=E], tf32-rounded
__device__ float g_Wt2[(size_t)E * FF];     // W2^T [N=E][K=FF], tf32-rounded
__device__ float g_WvT[(size_t)H * D * D];  // Wv^T [h][d][i] (i contiguous)

// ============================================================
// Helpers (arch-generic PTX: mma.sync / cp.async / ldmatrix)
// ============================================================
__device__ __forceinline__ uint32_t smem_u32(const void* p) {
    uint32_t a;
    asm("{ .reg .u64 t; cvta.to.shared.u64 t, %1; cvt.u32.u64 %0, t; }" : "=r"(a) : "l"(p));
    return a;
}
__device__ __forceinline__ float round_tf32(float x) {
    uint32_t u;
    asm("cvt.rna.tf32.f32 %0, %1;" : "=r"(u) : "f"(x));
    return __uint_as_float(u);
}
#define CP_ASYNC16(dst, src) \
    asm volatile("cp.async.cg.shared.global [%0], [%1], 16;" :: "r"(dst), "l"(src) : "memory")
#define CP_COMMIT() asm volatile("cp.async.commit_group;" ::: "memory")
template<int N> __device__ __forceinline__ void cp_wait() {
    asm volatile("cp.async.wait_group %0;" :: "n"(N) : "memory");
}
__device__ __forceinline__ void mma_tf32(float* c, const uint32_t* a, const uint32_t* b) {
    asm volatile(
        "mma.sync.aligned.m16n8k8.row.col.f32.tf32.tf32.f32 "
        "{%0,%1,%2,%3}, {%4,%5,%6,%7}, {%8,%9}, {%0,%1,%2,%3};"
        : "+f"(c[0]), "+f"(c[1]), "+f"(c[2]), "+f"(c[3])
        : "r"(a[0]), "r"(a[1]), "r"(a[2]), "r"(a[3]), "r"(b[0]), "r"(b[1]));
}
__device__ __forceinline__ void ldsm_x4(uint32_t* r, uint32_t addr) {
    asm volatile("ldmatrix.sync.aligned.m8n8.x4.shared.b16 {%0,%1,%2,%3}, [%4];"
        : "=r"(r[0]), "=r"(r[1]), "=r"(r[2]), "=r"(r[3]) : "r"(addr));
}

// ============================================================
// Kernel 0a: weight transpose + tf32 round: W[K][N] -> Wt[N][K]
// ============================================================
__global__ __launch_bounds__(256) void transpose_round_kernel(
    const float* __restrict__ W, float* __restrict__ Wt, int K, int N)
{
    __shared__ float t[32][33];
    const int n0 = blockIdx.x * 32;
    const int k0 = blockIdx.y * 32;
    const int tx = threadIdx.x & 31;
    const int ty = threadIdx.x >> 5;
    #pragma unroll
    for (int r = 0; r < 4; r++)
        t[ty + r * 8][tx] = round_tf32(W[(size_t)(k0 + ty + r * 8) * N + n0 + tx]);
    __syncthreads();
    #pragma unroll
    for (int r = 0; r < 4; r++)
        Wt[(size_t)(n0 + ty + r * 8) * K + k0 + tx] = t[tx][ty + r * 8];
}

// ============================================================
// Kernel 0b: Wv[h][i][d] -> WvT[h][d][i]
// ============================================================
__global__ __launch_bounds__(256) void transpose_wv_kernel(const float* __restrict__ Wv)
{
    __shared__ float t[64][65];
    const int h = blockIdx.x;
    const int tx = threadIdx.x & 63;
    const int ty = threadIdx.x >> 6;     // 0..3
    #pragma unroll
    for (int r = 0; r < 16; r++)
        t[ty + r * 4][tx] = Wv[(size_t)h * D * D + (ty + r * 4) * D + tx];
    __syncthreads();
    #pragma unroll
    for (int r = 0; r < 16; r++)
        g_WvT[(size_t)h * D * D + (ty + r * 4) * D + tx] = t[tx][ty + r * 4];
}

// ============================================================
// Kernel 1: LayerNorm + per-head V (D->D), Q/K (D->1) projections
// ============================================================
__global__ __launch_bounds__(256) void ln_proj_kernel(
    const float* __restrict__ x,
    const float* __restrict__ bv,
    const float* __restrict__ Wq, const float* __restrict__ bq,
    const float* __restrict__ Wk, const float* __restrict__ bk)
{
    __shared__ float xn[E];
    __shared__ float red[16];
    const int token = blockIdx.x;
    const int tid = threadIdx.x;
    const float* xin = x + (size_t)token * E;

    float v0 = xin[tid];
    float v1 = xin[tid + 256];
    float s = v0 + v1;
    float ss = v0 * v0 + v1 * v1;
    #pragma unroll
    for (int o = 16; o > 0; o >>= 1) {
        s  += __shfl_xor_sync(0xffffffffu, s, o);
        ss += __shfl_xor_sync(0xffffffffu, ss, o);
    }
    const int wid = tid >> 5, lid = tid & 31;
    if (lid == 0) { red[wid] = s; red[wid + 8] = ss; }
    __syncthreads();
    if (tid == 0) {
        float S1 = 0.f, S2 = 0.f;
        #pragma unroll
        for (int i = 0; i < 8; i++) { S1 += red[i]; S2 += red[i + 8]; }
        float mean = S1 * (1.0f / E);
        float var  = S2 * (1.0f / E) - mean * mean;
        red[0] = mean;
        red[1] = rsqrtf(var + 1e-5f);
    }
    __syncthreads();
    const float mean = red[0], rstd = red[1];
    xn[tid]       = (v0 - mean) * rstd;
    xn[tid + 256] = (v1 - mean) * rstd;
    __syncthreads();

    float* vout = g_V + (size_t)token * E;
    #pragma unroll
    for (int rep = 0; rep < 2; rep++) {
        const int e = tid + rep * 256;
        const int h = e >> 6, d = e & 63;
        const float* w  = g_WvT + (size_t)h * D * D + d * D;   // contiguous
        const float* xh = xn + h * D;
        float acc = bv[e];
        #pragma unroll
        for (int i = 0; i < D; i += 4) {
            const float4 w4 = *(const float4*)(w + i);
            acc = fmaf(xh[i],     w4.x, acc);
            acc = fmaf(xh[i + 1], w4.y, acc);
            acc = fmaf(xh[i + 2], w4.z, acc);
            acc = fmaf(xh[i + 3], w4.w, acc);
        }
        vout[e] = round_tf32(acc);
    }

    if (tid < 2 * H) {
        const int h = tid & 7;
        const bool isQ = tid < H;
        const float* w  = (isQ ? Wq : Wk) + h * D;
        const float* xh = xn + h * D;
        float acc = isQ ? bq[h] : bk[h];
        #pragma unroll
        for (int i = 0; i < D; i++) acc = fmaf(xh[i], w[i], acc);
        const int b = token >> 11, sidx = token & (S - 1);
        float* dst = isQ ? g_Q : g_K;
        dst[((size_t)b * H + h) * S + sidx] = acc;
    }
}

// ============================================================
// Kernel 2: attention, register-resident P.
// CTA: one (b,h), 128 queries; 8 warps each own 16q x 64d (full D).
// A-fragments of P computed directly in regs (exp), no P smem.
// den = register row-sum + 4-lane shfl butterfly.
// smem floats: Ksh[2048] | Vs[2][64][72]
// ============================================================
#define ATT_SMEM_FLOATS (2048 + 2*64*72)
#define ATT_SMEM_BYTES  (ATT_SMEM_FLOATS * 4)

__global__ __launch_bounds__(256) void attn_kernel()
{
    extern __shared__ float smem[];
    float* Ksh = smem;                // 2048
    float* Vs  = smem + 2048;         // 2*64*72

    const int bh = blockIdx.y;
    const int b = bh >> 3, h = bh & 7;
    const int q0 = blockIdx.x * 128;
    const int tid = threadIdx.x;
    const int lane = tid & 31, wid = tid >> 5;
    const uint32_t sbase = smem_u32(smem);
    const uint32_t vs_off = 2048u * 4u;

    for (int i = tid; i < S; i += 256) Ksh[i] = g_K[(size_t)bh * S + i];

    const int r0 = wid * 16 + (lane >> 2);       // query rows owned
    const float q_r0 = g_Q[(size_t)bh * S + q0 + r0];
    const float q_r1 = g_Q[(size_t)bh * S + q0 + r0 + 8];
    const int kl = lane & 3;
    const int nl = lane >> 2;

    const float* Vg = g_V + (size_t)b * S * E + h * D;
    auto loadV = [&](int kc, int buf) {
        #pragma unroll
        for (int p = 0; p < 4; p++) {
            const int r = (tid >> 4) + p * 16;
            const float* src = Vg + (size_t)(kc * 64 + r) * E + (tid & 15) * 4;
            const uint32_t dst = sbase + vs_off +
                (uint32_t)((buf * 4608 + r * 72 + (tid & 15) * 4) * 4);
            CP_ASYNC16(dst, src);
        }
    };

    loadV(0, 0);
    CP_COMMIT();

    float acc[8][4];
    #pragma unroll
    for (int j = 0; j < 8; j++)
        #pragma unroll
        for (int l = 0; l < 4; l++) acc[j][l] = 0.f;
    float den0 = 0.f, den1 = 0.f;

    const float cexp = -0.125f * 1.4426950408889634f;  // for exp2f

    const int NCH = S / 64;
    for (int kc = 0; kc < NCH; kc++) {
        const int buf = kc & 1;
        cp_wait<0>();
        __syncthreads();                       // Vs[buf] ready; all warps past prev chunk
        if (kc + 1 < NCH) { loadV(kc + 1, buf ^ 1); CP_COMMIT(); }

        const uint32_t* Vu = (const uint32_t*)(Vs + buf * 4608);
        #pragma unroll
        for (int ks = 0; ks < 8; ks++) {
            const int kk = kc * 64 + ks * 8 + kl;
            const float k0v = Ksh[kk];
            const float k1v = Ksh[kk + 4];
            float d00 = q_r0 - k0v, d10 = q_r1 - k0v;
            float d01 = q_r0 - k1v, d11 = q_r1 - k1v;
            float w00 = round_tf32(exp2f(d00 * d00 * cexp));
            float w10 = round_tf32(exp2f(d10 * d10 * cexp));
            float w01 = round_tf32(exp2f(d01 * d01 * cexp));
            float w11 = round_tf32(exp2f(d11 * d11 * cexp));
            den0 += w00 + w01;
            den1 += w10 + w11;
            uint32_t a[4] = { __float_as_uint(w00), __float_as_uint(w10),
                              __float_as_uint(w01), __float_as_uint(w11) };
            const int kidx = ks * 8 + kl;
            #pragma unroll
            for (int nt = 0; nt < 8; nt++) {
                uint32_t bb[2] = { Vu[kidx * 72 + nt * 8 + nl],
                                   Vu[(kidx + 4) * 72 + nt * 8 + nl] };
                mma_tf32(acc[nt], a, bb);
            }
        }
    }

    // denominator: butterfly over the 4 lanes sharing (lane>>2)
    den0 += __shfl_xor_sync(0xffffffffu, den0, 1);
    den0 += __shfl_xor_sync(0xffffffffu, den0, 2);
    den1 += __shfl_xor_sync(0xffffffffu, den1, 1);
    den1 += __shfl_xor_sync(0xffffffffu, den1, 2);
    const float inv0 = 1.0f / den0;
    const float inv1 = 1.0f / den1;

    // epilogue
    #pragma unroll
    for (int nt = 0; nt < 8; nt++) {
        const int col = nt * 8 + kl * 2;
        float2 v0, v1;
        v0.x = round_tf32(acc[nt][0] * inv0);
        v0.y = round_tf32(acc[nt][1] * inv0);
        v1.x = round_tf32(acc[nt][2] * inv1);
        v1.y = round_tf32(acc[nt][3] * inv1);
        const size_t t0 = ((size_t)b * S + q0 + r0) * E + h * D + col;
        const size_t t1 = ((size_t)b * S + q0 + r0 + 8) * E + h * D + col;
        *(float2*)&g_HO[t0] = v0;
        *(float2*)&g_HO[t1] = v1;
    }
}

// ============================================================
// Kernel 3/4: mma.sync tf32 GEMM (unchanged from R5 — it worked).
// ============================================================
#define GEMM_SMEM_BYTES (3 * 8192 * 4)

template<int MODE>
__global__ __launch_bounds__(256) void tc_gemm_kernel(
    const float* __restrict__ Bt, const float* __restrict__ bias,
    const float* __restrict__ res, float* __restrict__ Cout,
    int N, int K)
{
    extern __shared__ float smem[];
    const float* A = (MODE == 0) ? g_HO : g_MID;
    float* C = (MODE == 0) ? g_MID : Cout;

    const int tid = threadIdx.x;
    const int lane = tid & 31, wid = tid >> 5;
    const int bm = blockIdx.y * 128;
    const int bn = blockIdx.x * 128;
    const int wm = wid >> 2;
    const int wn = wid & 3;
    const uint32_t sbase = smem_u32(smem);

    const int lr = tid >> 3;
    const int lg = tid & 7;

    auto load_tile = [&](int kc, int st) {
        #pragma unroll
        for (int p = 0; p < 4; p++) {
            const int r = lr + p * 32;
            const uint32_t sw = (uint32_t)((st * 8192 + r * 32 + ((lg ^ (r & 7)) * 4)) * 4);
            CP_ASYNC16(sbase + sw, A  + (size_t)(bm + r) * K + kc * 32 + lg * 4);
            CP_ASYNC16(sbase + sw + 4096u * 4u, Bt + (size_t)(bn + r) * K + kc * 32 + lg * 4);
        }
    };

    const int lrow  = (lane & 7) + ((lane >> 3) & 1) * 8;
    const int lkoff = ((lane >> 3) & 2) * 2;
    const int cA = lkoff ^ ((lane & 7) * 4);
    const int bnrow = wn * 32 + (lane & 7) + ((lane >> 3) >> 1) * 8;
    const int bkoff = ((lane >> 3) & 1) * 4;
    const int cB = bkoff ^ ((lane & 7) * 4);
    uint32_t aRow[4];
    #pragma unroll
    for (int mt = 0; mt < 4; mt++)
        aRow[mt] = (uint32_t)((wm * 64 + mt * 16 + lrow) * 32 * 4);
    const uint32_t bRow0 = 4096u * 4u + (uint32_t)(bnrow * 32 * 4);
    const uint32_t bRow1 = bRow0 + 16u * 32u * 4u;

    float acc[4][4][4];
    #pragma unroll
    for (int i = 0; i < 4; i++)
        #pragma unroll
        for (int j = 0; j < 4; j++)
            #pragma unroll
            for (int l = 0; l < 4; l++) acc[i][j][l] = 0.f;

    const int nc = K / 32;
    load_tile(0, 0); CP_COMMIT();
    load_tile(1, 1); CP_COMMIT();

    for (int kc = 0; kc < nc; kc++) {
        const int st = kc % 3;
        if (kc + 1 < nc) cp_wait<1>(); else cp_wait<0>();
        __syncthreads();
        if (kc + 2 < nc) { load_tile(kc + 2, (kc + 2) % 3); CP_COMMIT(); }

        const uint32_t stb = sbase + (uint32_t)(st * 8192 * 4);
        #pragma unroll
        for (int ks = 0; ks < 4; ks++) {
            const uint32_t kA = (uint32_t)((((ks * 8) ^ cA)) * 4);
            const uint32_t kB = (uint32_t)((((ks * 8) ^ cB)) * 4);
            uint32_t a[4][4], b01[4], b23[4];
            #pragma unroll
            for (int mt = 0; mt < 4; mt++) ldsm_x4(a[mt], stb + aRow[mt] + kA);
            ldsm_x4(b01, stb + bRow0 + kB);
            ldsm_x4(b23, stb + bRow1 + kB);
            #pragma unroll
            for (int mt = 0; mt < 4; mt++) {
                mma_tf32(acc[mt][0], a[mt], b01);
                mma_tf32(acc[mt][1], a[mt], b01 + 2);
                mma_tf32(acc[mt][2], a[mt], b23);
                mma_tf32(acc[mt][3], a[mt], b23 + 2);
            }
        }
    }

    #pragma unroll
    for (int mt = 0; mt < 4; mt++) {
        const int r0 = bm + wm * 64 + mt * 16 + (lane >> 2);
        #pragma unroll
        for (int nt = 0; nt < 4; nt++) {
            const int col = bn + wn * 32 + nt * 8 + (lane & 3) * 2;
            const float bz0 = bias[col], bz1 = bias[col + 1];
            float c0 = acc[mt][nt][0] + bz0;
            float c1 = acc[mt][nt][1] + bz1;
            float c2 = acc[mt][nt][2] + bz0;
            float c3 = acc[mt][nt][3] + bz1;
            const size_t g0 = (size_t)r0 * N + col;
            const size_t g1 = (size_t)(r0 + 8) * N + col;
            if (MODE == 0) {
                c0 = round_tf32(c0 * normcdff(c0));
                c1 = round_tf32(c1 * normcdff(c1));
                c2 = round_tf32(c2 * normcdff(c2));
                c3 = round_tf32(c3 * normcdff(c3));
            } else {
                c0 += res[g0]; c1 += res[g0 + 1];
                c2 += res[g1]; c3 += res[g1 + 1];
            }
            float2 v0; v0.x = c0; v0.y = c1;
            float2 v1; v1.x = c2; v1.y = c3;
            *(float2*)&C[g0] = v0;
            *(float2*)&C[g1] = v1;
        }
    }
}

// ============================================================
extern "C" void kernel_launch(void* const* d_in, const int* in_sizes, int n_in,
                              void* d_out, int out_size)
{
    const float* input1 = (const float*)d_in[0];
    const float* Wv = (const float*)d_in[1];
    const float* bv = (const float*)d_in[2];
    const float* Wq = (const float*)d_in[3];
    const float* bq = (const float*)d_in[4];
    const float* Wk = (const float*)d_in[5];
    const float* bk = (const float*)d_in[6];
    const float* W1 = (const float*)d_in[7];
    const float* b1 = (const float*)d_in[8];
    const float* W2 = (const float*)d_in[9];
    const float* b2 = (const float*)d_in[10];
    float* out = (float*)d_out;

    float* s_Wt1; cudaGetSymbolAddress((void**)&s_Wt1, g_Wt1);
    float* s_Wt2; cudaGetSymbolAddress((void**)&s_Wt2, g_Wt2);

    cudaFuncSetAttribute(attn_kernel, cudaFuncAttributeMaxDynamicSharedMemorySize, ATT_SMEM_BYTES);
    cudaFuncSetAttribute(tc_gemm_kernel<0>, cudaFuncAttributeMaxDynamicSharedMemorySize, GEMM_SMEM_BYTES);
    cudaFuncSetAttribute(tc_gemm_kernel<1>, cudaFuncAttributeMaxDynamicSharedMemorySize, GEMM_SMEM_BYTES);

    transpose_wv_kernel<<<H, 256>>>(Wv);
    transpose_round_kernel<<<dim3(FF / 32, E / 32), 256>>>(W1, s_Wt1, E, FF);
    transpose_round_kernel<<<dim3(E / 32, FF / 32), 256>>>(W2, s_Wt2, FF, E);

    ln_proj_kernel<<<NTOK, 256>>>(input1, bv, Wq, bq, Wk, bk);
    attn_kernel<<<dim3(S / 128, B * H), 256, ATT_SMEM_BYTES>>>();

    tc_gemm_kernel<0><<<dim3(FF / 128, NTOK / 128), 256, GEMM_SMEM_BYTES>>>(s_Wt1, b1, nullptr, nullptr, FF, E);
    tc_gemm_kernel<1><<<dim3(E / 128, NTOK / 128), 256, GEMM_SMEM_BYTES>>>(s_Wt2, b2, input1, out, E, FF);
}

// round 7
// speedup vs baseline: 1.0036x; 1.0036x over previous
#include <cuda_runtime.h>
#include <math.h>
#include <stdint.h>

#define B 4
#define S 2048
#define E 512
#define H 8
#define D 64
#define FF 2048
#define NTOK (B*S)

// ---- device scratch (static, allocation-free) ----
__device__ float g_V[(size_t)NTOK * E];     // [b,s,h,d] token-major, tf32-rounded
__device__ float g_Q[(size_t)B * H * S];    // [b,h,s]
__device__ float g_K[(size_t)B * H * S];    // [b,h,s]
__device__ float g_HO[(size_t)NTOK * E];    // head_out [b,s,e], tf32-rounded
__device__ float g_MID[(size_t)NTOK * FF];  // GELU(h@W1+b1), tf32-rounded
__device__ float g_Wt1[(size_t)FF * E];     // W1^T [N=FF][K=E], tf32-rounded
__device__ float g_Wt2[(size_t)E * FF];     // W2^T [N=E][K=FF], tf32-rounded
__device__ float g_WvT[(size_t)H * D * D];  // Wv^T [h][d][i] (i contiguous)

// ============================================================
// Helpers (arch-generic PTX: mma.sync / cp.async / ldmatrix)
// ============================================================
__device__ __forceinline__ uint32_t smem_u32(const void* p) {
    uint32_t a;
    asm("{ .reg .u64 t; cvta.to.shared.u64 t, %1; cvt.u32.u64 %0, t; }" : "=r"(a) : "l"(p));
    return a;
}
__device__ __forceinline__ float round_tf32(float x) {
    uint32_t u;
    asm("cvt.rna.tf32.f32 %0, %1;" : "=r"(u) : "f"(x));
    return __uint_as_float(u);
}
#define CP_ASYNC16(dst, src) \
    asm volatile("cp.async.cg.shared.global [%0], [%1], 16;" :: "r"(dst), "l"(src) : "memory")
#define CP_COMMIT() asm volatile("cp.async.commit_group;" ::: "memory")
template<int N> __device__ __forceinline__ void cp_wait() {
    asm volatile("cp.async.wait_group %0;" :: "n"(N) : "memory");
}
__device__ __forceinline__ void mma_tf32(float* c, const uint32_t* a, const uint32_t* b) {
    asm volatile(
        "mma.sync.aligned.m16n8k8.row.col.f32.tf32.tf32.f32 "
        "{%0,%1,%2,%3}, {%4,%5,%6,%7}, {%8,%9}, {%0,%1,%2,%3};"
        : "+f"(c[0]), "+f"(c[1]), "+f"(c[2]), "+f"(c[3])
        : "r"(a[0]), "r"(a[1]), "r"(a[2]), "r"(a[3]), "r"(b[0]), "r"(b[1]));
}
__device__ __forceinline__ void ldsm_x4(uint32_t* r, uint32_t addr) {
    asm volatile("ldmatrix.sync.aligned.m8n8.x4.shared.b16 {%0,%1,%2,%3}, [%4];"
        : "=r"(r[0]), "=r"(r[1]), "=r"(r[2]), "=r"(r[3]) : "r"(addr));
}

// ============================================================
// Kernel 0a: weight transpose + tf32 round: W[K][N] -> Wt[N][K]
// ============================================================
__global__ __launch_bounds__(256) void transpose_round_kernel(
    const float* __restrict__ W, float* __restrict__ Wt, int K, int N)
{
    __shared__ float t[32][33];
    const int n0 = blockIdx.x * 32;
    const int k0 = blockIdx.y * 32;
    const int tx = threadIdx.x & 31;
    const int ty = threadIdx.x >> 5;
    #pragma unroll
    for (int r = 0; r < 4; r++)
        t[ty + r * 8][tx] = round_tf32(W[(size_t)(k0 + ty + r * 8) * N + n0 + tx]);
    __syncthreads();
    #pragma unroll
    for (int r = 0; r < 4; r++)
        Wt[(size_t)(n0 + ty + r * 8) * K + k0 + tx] = t[tx][ty + r * 8];
}

// ============================================================
// Kernel 0b: Wv[h][i][d] -> WvT[h][d][i]
// ============================================================
__global__ __launch_bounds__(256) void transpose_wv_kernel(const float* __restrict__ Wv)
{
    __shared__ float t[64][65];
    const int h = blockIdx.x;
    const int tx = threadIdx.x & 63;
    const int ty = threadIdx.x >> 6;     // 0..3
    #pragma unroll
    for (int r = 0; r < 16; r++)
        t[ty + r * 4][tx] = Wv[(size_t)h * D * D + (ty + r * 4) * D + tx];
    __syncthreads();
    #pragma unroll
    for (int r = 0; r < 16; r++)
        g_WvT[(size_t)h * D * D + (ty + r * 4) * D + tx] = t[tx][ty + r * 4];
}

// ============================================================
// Kernel 1: LayerNorm + per-head V (D->D), Q/K (D->1) projections
// ============================================================
__global__ __launch_bounds__(256) void ln_proj_kernel(
    const float* __restrict__ x,
    const float* __restrict__ bv,
    const float* __restrict__ Wq, const float* __restrict__ bq,
    const float* __restrict__ Wk, const float* __restrict__ bk)
{
    __shared__ float xn[E];
    __shared__ float red[16];
    const int token = blockIdx.x;
    const int tid = threadIdx.x;
    const float* xin = x + (size_t)token * E;

    float v0 = xin[tid];
    float v1 = xin[tid + 256];
    float s = v0 + v1;
    float ss = v0 * v0 + v1 * v1;
    #pragma unroll
    for (int o = 16; o > 0; o >>= 1) {
        s  += __shfl_xor_sync(0xffffffffu, s, o);
        ss += __shfl_xor_sync(0xffffffffu, ss, o);
    }
    const int wid = tid >> 5, lid = tid & 31;
    if (lid == 0) { red[wid] = s; red[wid + 8] = ss; }
    __syncthreads();
    if (tid == 0) {
        float S1 = 0.f, S2 = 0.f;
        #pragma unroll
        for (int i = 0; i < 8; i++) { S1 += red[i]; S2 += red[i + 8]; }
        float mean = S1 * (1.0f / E);
        float var  = S2 * (1.0f / E) - mean * mean;
        red[0] = mean;
        red[1] = rsqrtf(var + 1e-5f);
    }
    __syncthreads();
    const float mean = red[0], rstd = red[1];
    xn[tid]       = (v0 - mean) * rstd;
    xn[tid + 256] = (v1 - mean) * rstd;
    __syncthreads();

    float* vout = g_V + (size_t)token * E;
    #pragma unroll
    for (int rep = 0; rep < 2; rep++) {
        const int e = tid + rep * 256;
        const int h = e >> 6, d = e & 63;
        const float* w  = g_WvT + (size_t)h * D * D + d * D;   // contiguous
        const float* xh = xn + h * D;
        float acc = bv[e];
        #pragma unroll
        for (int i = 0; i < D; i += 4) {
            const float4 w4 = *(const float4*)(w + i);
            acc = fmaf(xh[i],     w4.x, acc);
            acc = fmaf(xh[i + 1], w4.y, acc);
            acc = fmaf(xh[i + 2], w4.z, acc);
            acc = fmaf(xh[i + 3], w4.w, acc);
        }
        vout[e] = round_tf32(acc);
    }

    if (tid < 2 * H) {
        const int h = tid & 7;
        const bool isQ = tid < H;
        const float* w  = (isQ ? Wq : Wk) + h * D;
        const float* xh = xn + h * D;
        float acc = isQ ? bq[h] : bk[h];
        #pragma unroll
        for (int i = 0; i < D; i++) acc = fmaf(xh[i], w[i], acc);
        const int b = token >> 11, sidx = token & (S - 1);
        float* dst = isQ ? g_Q : g_K;
        dst[((size_t)b * H + h) * S + sidx] = acc;
    }
}

// ============================================================
// Kernel 2: attention, register-resident P.
// CTA: one (b,h), 128 queries; 8 warps each own 16q x 64d (full D).
// A-fragments of P computed directly in regs (exp), no P smem.
// den = register row-sum + 4-lane shfl butterfly.
// smem floats: Ksh[2048] | Vs[2][64][72]
// ============================================================
#define ATT_SMEM_FLOATS (2048 + 2*64*72)
#define ATT_SMEM_BYTES  (ATT_SMEM_FLOATS * 4)

__global__ __launch_bounds__(256) void attn_kernel()
{
    extern __shared__ float smem[];
    float* Ksh = smem;                // 2048
    float* Vs  = smem + 2048;         // 2*64*72

    const int bh = blockIdx.y;
    const int b = bh >> 3, h = bh & 7;
    const int q0 = blockIdx.x * 128;
    const int tid = threadIdx.x;
    const int lane = tid & 31, wid = tid >> 5;
    const uint32_t sbase = smem_u32(smem);
    const uint32_t vs_off = 2048u * 4u;

    for (int i = tid; i < S; i += 256) Ksh[i] = g_K[(size_t)bh * S + i];

    const int r0 = wid * 16 + (lane >> 2);       // query rows owned
    const float q_r0 = g_Q[(size_t)bh * S + q0 + r0];
    const float q_r1 = g_Q[(size_t)bh * S + q0 + r0 + 8];
    const int kl = lane & 3;
    const int nl = lane >> 2;

    const float* Vg = g_V + (size_t)b * S * E + h * D;
    auto loadV = [&](int kc, int buf) {
        #pragma unroll
        for (int p = 0; p < 4; p++) {
            const int r = (tid >> 4) + p * 16;
            const float* src = Vg + (size_t)(kc * 64 + r) * E + (tid & 15) * 4;
            const uint32_t dst = sbase + vs_off +
                (uint32_t)((buf * 4608 + r * 72 + (tid & 15) * 4) * 4);
            CP_ASYNC16(dst, src);
        }
    };

    loadV(0, 0);
    CP_COMMIT();

    float acc[8][4];
    #pragma unroll
    for (int j = 0; j < 8; j++)
        #pragma unroll
        for (int l = 0; l < 4; l++) acc[j][l] = 0.f;
    float den0 = 0.f, den1 = 0.f;

    const float cexp = -0.125f * 1.4426950408889634f;  // for exp2f

    const int NCH = S / 64;
    for (int kc = 0; kc < NCH; kc++) {
        const int buf = kc & 1;
        cp_wait<0>();
        __syncthreads();                       // Vs[buf] ready; all warps past prev chunk
        if (kc + 1 < NCH) { loadV(kc + 1, buf ^ 1); CP_COMMIT(); }

        const uint32_t* Vu = (const uint32_t*)(Vs + buf * 4608);
        #pragma unroll
        for (int ks = 0; ks < 8; ks++) {
            const int kk = kc * 64 + ks * 8 + kl;
            const float k0v = Ksh[kk];
            const float k1v = Ksh[kk + 4];
            float d00 = q_r0 - k0v, d10 = q_r1 - k0v;
            float d01 = q_r0 - k1v, d11 = q_r1 - k1v;
            float w00 = round_tf32(exp2f(d00 * d00 * cexp));
            float w10 = round_tf32(exp2f(d10 * d10 * cexp));
            float w01 = round_tf32(exp2f(d01 * d01 * cexp));
            float w11 = round_tf32(exp2f(d11 * d11 * cexp));
            den0 += w00 + w01;
            den1 += w10 + w11;
            uint32_t a[4] = { __float_as_uint(w00), __float_as_uint(w10),
                              __float_as_uint(w01), __float_as_uint(w11) };
            const int kidx = ks * 8 + kl;
            #pragma unroll
            for (int nt = 0; nt < 8; nt++) {
                uint32_t bb[2] = { Vu[kidx * 72 + nt * 8 + nl],
                                   Vu[(kidx + 4) * 72 + nt * 8 + nl] };
                mma_tf32(acc[nt], a, bb);
            }
        }
    }

    // denominator: butterfly over the 4 lanes sharing (lane>>2)
    den0 += __shfl_xor_sync(0xffffffffu, den0, 1);
    den0 += __shfl_xor_sync(0xffffffffu, den0, 2);
    den1 += __shfl_xor_sync(0xffffffffu, den1, 1);
    den1 += __shfl_xor_sync(0xffffffffu, den1, 2);
    const float inv0 = 1.0f / den0;
    const float inv1 = 1.0f / den1;

    // epilogue
    #pragma unroll
    for (int nt = 0; nt < 8; nt++) {
        const int col = nt * 8 + kl * 2;
        float2 v0, v1;
        v0.x = round_tf32(acc[nt][0] * inv0);
        v0.y = round_tf32(acc[nt][1] * inv0);
        v1.x = round_tf32(acc[nt][2] * inv1);
        v1.y = round_tf32(acc[nt][3] * inv1);
        const size_t t0 = ((size_t)b * S + q0 + r0) * E + h * D + col;
        const size_t t1 = ((size_t)b * S + q0 + r0 + 8) * E + h * D + col;
        *(float2*)&g_HO[t0] = v0;
        *(float2*)&g_HO[t1] = v1;
    }
}

// ============================================================
// Kernel 3/4: mma.sync tf32 GEMM (unchanged from R5 — it worked).
// ============================================================
#define GEMM_SMEM_BYTES (3 * 8192 * 4)

template<int MODE>
__global__ __launch_bounds__(256) void tc_gemm_kernel(
    const float* __restrict__ Bt, const float* __restrict__ bias,
    const float* __restrict__ res, float* __restrict__ Cout,
    int N, int K)
{
    extern __shared__ float smem[];
    const float* A = (MODE == 0) ? g_HO : g_MID;
    float* C = (MODE == 0) ? g_MID : Cout;

    const int tid = threadIdx.x;
    const int lane = tid & 31, wid = tid >> 5;
    const int bm = blockIdx.y * 128;
    const int bn = blockIdx.x * 128;
    const int wm = wid >> 2;
    const int wn = wid & 3;
    const uint32_t sbase = smem_u32(smem);

    const int lr = tid >> 3;
    const int lg = tid & 7;

    auto load_tile = [&](int kc, int st) {
        #pragma unroll
        for (int p = 0; p < 4; p++) {
            const int r = lr + p * 32;
            const uint32_t sw = (uint32_t)((st * 8192 + r * 32 + ((lg ^ (r & 7)) * 4)) * 4);
            CP_ASYNC16(sbase + sw, A  + (size_t)(bm + r) * K + kc * 32 + lg * 4);
            CP_ASYNC16(sbase + sw + 4096u * 4u, Bt + (size_t)(bn + r) * K + kc * 32 + lg * 4);
        }
    };

    const int lrow  = (lane & 7) + ((lane >> 3) & 1) * 8;
    const int lkoff = ((lane >> 3) & 2) * 2;
    const int cA = lkoff ^ ((lane & 7) * 4);
    const int bnrow = wn * 32 + (lane & 7) + ((lane >> 3) >> 1) * 8;
    const int bkoff = ((lane >> 3) & 1) * 4;
    const int cB = bkoff ^ ((lane & 7) * 4);
    uint32_t aRow[4];
    #pragma unroll
    for (int mt = 0; mt < 4; mt++)
        aRow[mt] = (uint32_t)((wm * 64 + mt * 16 + lrow) * 32 * 4);
    const uint32_t bRow0 = 4096u * 4u + (uint32_t)(bnrow * 32 * 4);
    const uint32_t bRow1 = bRow0 + 16u * 32u * 4u;

    float acc[4][4][4];
    #pragma unroll
    for (int i = 0; i < 4; i++)
        #pragma unroll
        for (int j = 0; j < 4; j++)
            #pragma unroll
            for (int l = 0; l < 4; l++) acc[i][j][l] = 0.f;

    const int nc = K / 32;
    load_tile(0, 0); CP_COMMIT();
    load_tile(1, 1); CP_COMMIT();

    for (int kc = 0; kc < nc; kc++) {
        const int st = kc % 3;
        if (kc + 1 < nc) cp_wait<1>(); else cp_wait<0>();
        __syncthreads();
        if (kc + 2 < nc) { load_tile(kc + 2, (kc + 2) % 3); CP_COMMIT(); }

        const uint32_t stb = sbase + (uint32_t)(st * 8192 * 4);
        #pragma unroll
        for (int ks = 0; ks < 4; ks++) {
            const uint32_t kA = (uint32_t)((((ks * 8) ^ cA)) * 4);
            const uint32_t kB = (uint32_t)((((ks * 8) ^ cB)) * 4);
            uint32_t a[4][4], b01[4], b23[4];
            #pragma unroll
            for (int mt = 0; mt < 4; mt++) ldsm_x4(a[mt], stb + aRow[mt] + kA);
            ldsm_x4(b01, stb + bRow0 + kB);
            ldsm_x4(b23, stb + bRow1 + kB);
            #pragma unroll
            for (int mt = 0; mt < 4; mt++) {
                mma_tf32(acc[mt][0], a[mt], b01);
                mma_tf32(acc[mt][1], a[mt], b01 + 2);
                mma_tf32(acc[mt][2], a[mt], b23);
                mma_tf32(acc[mt][3], a[mt], b23 + 2);
            }
        }
    }

    #pragma unroll
    for (int mt = 0; mt < 4; mt++) {
        const int r0 = bm + wm * 64 + mt * 16 + (lane >> 2);
        #pragma unroll
        for (int nt = 0; nt < 4; nt++) {
            const int col = bn + wn * 32 + nt * 8 + (lane & 3) * 2;
            const float bz0 = bias[col], bz1 = bias[col + 1];
            float c0 = acc[mt][nt][0] + bz0;
            float c1 = acc[mt][nt][1] + bz1;
            float c2 = acc[mt][nt][2] + bz0;
            float c3 = acc[mt][nt][3] + bz1;
            const size_t g0 = (size_t)r0 * N + col;
            const size_t g1 = (size_t)(r0 + 8) * N + col;
            if (MODE == 0) {
                c0 = round_tf32(c0 * normcdff(c0));
                c1 = round_tf32(c1 * normcdff(c1));
                c2 = round_tf32(c2 * normcdff(c2));
                c3 = round_tf32(c3 * normcdff(c3));
            } else {
                c0 += res[g0]; c1 += res[g0 + 1];
                c2 += res[g1]; c3 += res[g1 + 1];
            }
            float2 v0; v0.x = c0; v0.y = c1;
            float2 v1; v1.x = c2; v1.y = c3;
            *(float2*)&C[g0] = v0;
            *(float2*)&C[g1] = v1;
        }
    }
}

// ============================================================
extern "C" void kernel_launch(void* const* d_in, const int* in_sizes, int n_in,
                              void* d_out, int out_size)
{
    const float* input1 = (const float*)d_in[0];
    const float* Wv = (const float*)d_in[1];
    const float* bv = (const float*)d_in[2];
    const float* Wq = (const float*)d_in[3];
    const float* bq = (const float*)d_in[4];
    const float* Wk = (const float*)d_in[5];
    const float* bk = (const float*)d_in[6];
    const float* W1 = (const float*)d_in[7];
    const float* b1 = (const float*)d_in[8];
    const float* W2 = (const float*)d_in[9];
    const float* b2 = (const float*)d_in[10];
    float* out = (float*)d_out;

    float* s_Wt1; cudaGetSymbolAddress((void**)&s_Wt1, g_Wt1);
    float* s_Wt2; cudaGetSymbolAddress((void**)&s_Wt2, g_Wt2);

    cudaFuncSetAttribute(attn_kernel, cudaFuncAttributeMaxDynamicSharedMemorySize, ATT_SMEM_BYTES);
    cudaFuncSetAttribute(tc_gemm_kernel<0>, cudaFuncAttributeMaxDynamicSharedMemorySize, GEMM_SMEM_BYTES);
    cudaFuncSetAttribute(tc_gemm_kernel<1>, cudaFuncAttributeMaxDynamicSharedMemorySize, GEMM_SMEM_BYTES);

    transpose_wv_kernel<<<H, 256>>>(Wv);
    transpose_round_kernel<<<dim3(FF / 32, E / 32), 256>>>(W1, s_Wt1, E, FF);
    transpose_round_kernel<<<dim3(E / 32, FF / 32), 256>>>(W2, s_Wt2, FF, E);

    ln_proj_kernel<<<NTOK, 256>>>(input1, bv, Wq, bq, Wk, bk);
    attn_kernel<<<dim3(S / 128, B * H), 256, ATT_SMEM_BYTES>>>();

    tc_gemm_kernel<0><<<dim3(FF / 128, NTOK / 128), 256, GEMM_SMEM_BYTES>>>(s_Wt1, b1, nullptr, nullptr, FF, E);
    tc_gemm_kernel<1><<<dim3(E / 128, NTOK / 128), 256, GEMM_SMEM_BYTES>>>(s_Wt2, b2, input1, out, E, FF);
}

// round 8
// speedup vs baseline: 1.4618x; 1.4565x over previous
#include <cuda_runtime.h>
#include <math.h>
#include <stdint.h>

#define B 4
#define S 2048
#define E 512
#define H 8
#define D 64
#define FF 2048
#define NTOK (B*S)

// ---- device scratch (static, allocation-free) ----
__device__ float g_V[(size_t)NTOK * E];     // [b,s,h,d] token-major, tf32-rounded
__device__ float g_Q[(size_t)B * H * S];    // [b,h,s]
__device__ float g_K[(size_t)B * H * S];    // [b,h,s]
__device__ float g_HO[(size_t)NTOK * E];    // head_out [b,s,e], tf32-rounded
__device__ float g_MID[(size_t)NTOK * FF];  // GELU(h@W1+b1), tf32-rounded
__device__ float g_Wt1[(size_t)FF * E];     // W1^T [N=FF][K=E], tf32-rounded
__device__ float g_Wt2[(size_t)E * FF];     // W2^T [N=E][K=FF], tf32-rounded

// ============================================================
// Helpers (arch-generic PTX: mma.sync / cp.async / ldmatrix)
// ============================================================
__device__ __forceinline__ uint32_t smem_u32(const void* p) {
    uint32_t a;
    asm("{ .reg .u64 t; cvta.to.shared.u64 t, %1; cvt.u32.u64 %0, t; }" : "=r"(a) : "l"(p));
    return a;
}
__device__ __forceinline__ float round_tf32(float x) {
    uint32_t u;
    asm("cvt.rna.tf32.f32 %0, %1;" : "=r"(u) : "f"(x));
    return __uint_as_float(u);
}
#define CP_ASYNC16(dst, src) \
    asm volatile("cp.async.cg.shared.global [%0], [%1], 16;" :: "r"(dst), "l"(src) : "memory")
#define CP_COMMIT() asm volatile("cp.async.commit_group;" ::: "memory")
template<int N> __device__ __forceinline__ void cp_wait() {
    asm volatile("cp.async.wait_group %0;" :: "n"(N) : "memory");
}
__device__ __forceinline__ void mma_tf32(float* c, const uint32_t* a, const uint32_t* b) {
    asm volatile(
        "mma.sync.aligned.m16n8k8.row.col.f32.tf32.tf32.f32 "
        "{%0,%1,%2,%3}, {%4,%5,%6,%7}, {%8,%9}, {%0,%1,%2,%3};"
        : "+f"(c[0]), "+f"(c[1]), "+f"(c[2]), "+f"(c[3])
        : "r"(a[0]), "r"(a[1]), "r"(a[2]), "r"(a[3]), "r"(b[0]), "r"(b[1]));
}
__device__ __forceinline__ void ldsm_x4(uint32_t* r, uint32_t addr) {
    asm volatile("ldmatrix.sync.aligned.m8n8.x4.shared.b16 {%0,%1,%2,%3}, [%4];"
        : "=r"(r[0]), "=r"(r[1]), "=r"(r[2]), "=r"(r[3]) : "r"(addr));
}

// ============================================================
// Kernel 0: weight transpose + tf32 round: W[K][N] -> Wt[N][K]
// ============================================================
__global__ __launch_bounds__(256) void transpose_round_kernel(
    const float* __restrict__ W, float* __restrict__ Wt, int K, int N)
{
    __shared__ float t[32][33];
    const int n0 = blockIdx.x * 32;
    const int k0 = blockIdx.y * 32;
    const int tx = threadIdx.x & 31;
    const int ty = threadIdx.x >> 5;
    #pragma unroll
    for (int r = 0; r < 4; r++)
        t[ty + r * 8][tx] = round_tf32(W[(size_t)(k0 + ty + r * 8) * N + n0 + tx]);
    __syncthreads();
    #pragma unroll
    for (int r = 0; r < 4; r++)
        Wt[(size_t)(n0 + ty + r * 8) * K + k0 + tx] = t[tx][ty + r * 8];
}

// ============================================================
// Kernel 1: LayerNorm + projections, 32 tokens per CTA.
// Phase 1: LN of 32 tokens into smem xn[32][512] (warp per 4 tokens).
// Phase 2: V proj — thread owns (h,d); streams Wv[h][i][d] ONCE
//          (coalesced: fixed i, consecutive d across warp), FMAs into
//          32 token-accumulators (xn reads are warp-uniform broadcasts).
// Phase 3: Q/K scalar projections (thread = token x head).
// dynamic smem: 32*512 floats = 64 KB.
// ============================================================
#define LN_SMEM_BYTES (32 * 512 * 4)

__global__ __launch_bounds__(256) void ln_proj_kernel(
    const float* __restrict__ x,
    const float* __restrict__ Wv, const float* __restrict__ bv,
    const float* __restrict__ Wq, const float* __restrict__ bq,
    const float* __restrict__ Wk, const float* __restrict__ bk)
{
    extern __shared__ float smem[];
    float (*xn)[512] = (float(*)[512])smem;

    const int tb = blockIdx.x * 32;
    const int tid = threadIdx.x;
    const int lane = tid & 31, wid = tid >> 5;

    // ---- Phase 1: LN (each warp: 4 tokens) ----
    #pragma unroll
    for (int tt = 0; tt < 4; tt++) {
        const int t = wid * 4 + tt;
        const float* xin = x + (size_t)(tb + t) * E;
        float v[16];
        float s = 0.f, ss = 0.f;
        #pragma unroll
        for (int j = 0; j < 16; j++) {
            v[j] = xin[lane + j * 32];
            s += v[j];
            ss = fmaf(v[j], v[j], ss);
        }
        #pragma unroll
        for (int o = 16; o > 0; o >>= 1) {
            s  += __shfl_xor_sync(0xffffffffu, s, o);
            ss += __shfl_xor_sync(0xffffffffu, ss, o);
        }
        const float mean = s * (1.0f / E);
        const float var  = ss * (1.0f / E) - mean * mean;
        const float rstd = rsqrtf(var + 1e-5f);
        #pragma unroll
        for (int j = 0; j < 16; j++)
            xn[t][lane + j * 32] = (v[j] - mean) * rstd;
    }
    __syncthreads();

    // ---- Phase 2: V projection, 32 tokens per thread-column ----
    #pragma unroll
    for (int rep = 0; rep < 2; rep++) {
        const int e = tid + rep * 256;
        const int h = e >> 6, d = e & 63;
        const float* w = Wv + (size_t)h * D * D + d;  // stride D over i (coalesced)
        const float bvv = bv[e];
        float acc[32];
        #pragma unroll
        for (int t = 0; t < 32; t++) acc[t] = bvv;
        const float* xh = &xn[0][h * 64];
        #pragma unroll 4
        for (int i = 0; i < D; i++) {
            const float wi = w[i * D];
            #pragma unroll
            for (int t = 0; t < 32; t++)
                acc[t] = fmaf(xh[t * 512 + i], wi, acc[t]);
        }
        #pragma unroll 4
        for (int t = 0; t < 32; t++)
            g_V[(size_t)(tb + t) * E + e] = round_tf32(acc[t]);
    }

    // ---- Phase 3: Q/K (thread = token x head) ----
    {
        const int t = tid >> 3, h = tid & 7;
        const float* wq = Wq + h * D;
        const float* wk = Wk + h * D;
        const float* xh = xn[t] + h * 64;
        float accq = bq[h], acck = bk[h];
        #pragma unroll
        for (int i = 0; i < D; i++) {
            const float xv = xh[i];
            accq = fmaf(xv, wq[i], accq);
            acck = fmaf(xv, wk[i], acck);
        }
        const int token = tb + t;
        const int b = token >> 11, sidx = token & (S - 1);
        g_Q[((size_t)b * H + h) * S + sidx] = accq;
        g_K[((size_t)b * H + h) * S + sidx] = acck;
    }
}

// ============================================================
// Kernel 2: attention, register-resident P (R7 version — keep).
// CTA: one (b,h), 128 queries; 8 warps each own 16q x 64d (full D).
// smem floats: Ksh[2048] | Vs[2][64][72]
// ============================================================
#define ATT_SMEM_FLOATS (2048 + 2*64*72)
#define ATT_SMEM_BYTES  (ATT_SMEM_FLOATS * 4)

__global__ __launch_bounds__(256) void attn_kernel()
{
    extern __shared__ float smem[];
    float* Ksh = smem;                // 2048
    float* Vs  = smem + 2048;         // 2*64*72

    const int bh = blockIdx.y;
    const int b = bh >> 3, h = bh & 7;
    const int q0 = blockIdx.x * 128;
    const int tid = threadIdx.x;
    const int lane = tid & 31, wid = tid >> 5;
    const uint32_t sbase = smem_u32(smem);
    const uint32_t vs_off = 2048u * 4u;

    for (int i = tid; i < S; i += 256) Ksh[i] = g_K[(size_t)bh * S + i];

    const int r0 = wid * 16 + (lane >> 2);
    const float q_r0 = g_Q[(size_t)bh * S + q0 + r0];
    const float q_r1 = g_Q[(size_t)bh * S + q0 + r0 + 8];
    const int kl = lane & 3;
    const int nl = lane >> 2;

    const float* Vg = g_V + (size_t)b * S * E + h * D;
    auto loadV = [&](int kc, int buf) {
        #pragma unroll
        for (int p = 0; p < 4; p++) {
            const int r = (tid >> 4) + p * 16;
            const float* src = Vg + (size_t)(kc * 64 + r) * E + (tid & 15) * 4;
            const uint32_t dst = sbase + vs_off +
                (uint32_t)((buf * 4608 + r * 72 + (tid & 15) * 4) * 4);
            CP_ASYNC16(dst, src);
        }
    };

    loadV(0, 0);
    CP_COMMIT();

    float acc[8][4];
    #pragma unroll
    for (int j = 0; j < 8; j++)
        #pragma unroll
        for (int l = 0; l < 4; l++) acc[j][l] = 0.f;
    float den0 = 0.f, den1 = 0.f;

    const float cexp = -0.125f * 1.4426950408889634f;

    const int NCH = S / 64;
    for (int kc = 0; kc < NCH; kc++) {
        const int buf = kc & 1;
        cp_wait<0>();
        __syncthreads();
        if (kc + 1 < NCH) { loadV(kc + 1, buf ^ 1); CP_COMMIT(); }

        const uint32_t* Vu = (const uint32_t*)(Vs + buf * 4608);
        #pragma unroll
        for (int ks = 0; ks < 8; ks++) {
            const int kk = kc * 64 + ks * 8 + kl;
            const float k0v = Ksh[kk];
            const float k1v = Ksh[kk + 4];
            float d00 = q_r0 - k0v, d10 = q_r1 - k0v;
            float d01 = q_r0 - k1v, d11 = q_r1 - k1v;
            float w00 = round_tf32(exp2f(d00 * d00 * cexp));
            float w10 = round_tf32(exp2f(d10 * d10 * cexp));
            float w01 = round_tf32(exp2f(d01 * d01 * cexp));
            float w11 = round_tf32(exp2f(d11 * d11 * cexp));
            den0 += w00 + w01;
            den1 += w10 + w11;
            uint32_t a[4] = { __float_as_uint(w00), __float_as_uint(w10),
                              __float_as_uint(w01), __float_as_uint(w11) };
            const int kidx = ks * 8 + kl;
            #pragma unroll
            for (int nt = 0; nt < 8; nt++) {
                uint32_t bb[2] = { Vu[kidx * 72 + nt * 8 + nl],
                                   Vu[(kidx + 4) * 72 + nt * 8 + nl] };
                mma_tf32(acc[nt], a, bb);
            }
        }
    }

    den0 += __shfl_xor_sync(0xffffffffu, den0, 1);
    den0 += __shfl_xor_sync(0xffffffffu, den0, 2);
    den1 += __shfl_xor_sync(0xffffffffu, den1, 1);
    den1 += __shfl_xor_sync(0xffffffffu, den1, 2);
    const float inv0 = 1.0f / den0;
    const float inv1 = 1.0f / den1;

    #pragma unroll
    for (int nt = 0; nt < 8; nt++) {
        const int col = nt * 8 + kl * 2;
        float2 v0, v1;
        v0.x = round_tf32(acc[nt][0] * inv0);
        v0.y = round_tf32(acc[nt][1] * inv0);
        v1.x = round_tf32(acc[nt][2] * inv1);
        v1.y = round_tf32(acc[nt][3] * inv1);
        const size_t t0 = ((size_t)b * S + q0 + r0) * E + h * D + col;
        const size_t t1 = ((size_t)b * S + q0 + r0 + 8) * E + h * D + col;
        *(float2*)&g_HO[t0] = v0;
        *(float2*)&g_HO[t1] = v1;
    }
}

// ============================================================
// Kernel 3/4: mma.sync tf32 GEMM (R5 version — keep).
// ============================================================
#define GEMM_SMEM_BYTES (3 * 8192 * 4)

template<int MODE>
__global__ __launch_bounds__(256) void tc_gemm_kernel(
    const float* __restrict__ Bt, const float* __restrict__ bias,
    const float* __restrict__ res, float* __restrict__ Cout,
    int N, int K)
{
    extern __shared__ float smem[];
    const float* A = (MODE == 0) ? g_HO : g_MID;
    float* C = (MODE == 0) ? g_MID : Cout;

    const int tid = threadIdx.x;
    const int lane = tid & 31, wid = tid >> 5;
    const int bm = blockIdx.y * 128;
    const int bn = blockIdx.x * 128;
    const int wm = wid >> 2;
    const int wn = wid & 3;
    const uint32_t sbase = smem_u32(smem);

    const int lr = tid >> 3;
    const int lg = tid & 7;

    auto load_tile = [&](int kc, int st) {
        #pragma unroll
        for (int p = 0; p < 4; p++) {
            const int r = lr + p * 32;
            const uint32_t sw = (uint32_t)((st * 8192 + r * 32 + ((lg ^ (r & 7)) * 4)) * 4);
            CP_ASYNC16(sbase + sw, A  + (size_t)(bm + r) * K + kc * 32 + lg * 4);
            CP_ASYNC16(sbase + sw + 4096u * 4u, Bt + (size_t)(bn + r) * K + kc * 32 + lg * 4);
        }
    };

    const int lrow  = (lane & 7) + ((lane >> 3) & 1) * 8;
    const int lkoff = ((lane >> 3) & 2) * 2;
    const int cA = lkoff ^ ((lane & 7) * 4);
    const int bnrow = wn * 32 + (lane & 7) + ((lane >> 3) >> 1) * 8;
    const int bkoff = ((lane >> 3) & 1) * 4;
    const int cB = bkoff ^ ((lane & 7) * 4);
    uint32_t aRow[4];
    #pragma unroll
    for (int mt = 0; mt < 4; mt++)
        aRow[mt] = (uint32_t)((wm * 64 + mt * 16 + lrow) * 32 * 4);
    const uint32_t bRow0 = 4096u * 4u + (uint32_t)(bnrow * 32 * 4);
    const uint32_t bRow1 = bRow0 + 16u * 32u * 4u;

    float acc[4][4][4];
    #pragma unroll
    for (int i = 0; i < 4; i++)
        #pragma unroll
        for (int j = 0; j < 4; j++)
            #pragma unroll
            for (int l = 0; l < 4; l++) acc[i][j][l] = 0.f;

    const int nc = K / 32;
    load_tile(0, 0); CP_COMMIT();
    load_tile(1, 1); CP_COMMIT();

    for (int kc = 0; kc < nc; kc++) {
        const int st = kc % 3;
        if (kc + 1 < nc) cp_wait<1>(); else cp_wait<0>();
        __syncthreads();
        if (kc + 2 < nc) { load_tile(kc + 2, (kc + 2) % 3); CP_COMMIT(); }

        const uint32_t stb = sbase + (uint32_t)(st * 8192 * 4);
        #pragma unroll
        for (int ks = 0; ks < 4; ks++) {
            const uint32_t kA = (uint32_t)((((ks * 8) ^ cA)) * 4);
            const uint32_t kB = (uint32_t)((((ks * 8) ^ cB)) * 4);
            uint32_t a[4][4], b01[4], b23[4];
            #pragma unroll
            for (int mt = 0; mt < 4; mt++) ldsm_x4(a[mt], stb + aRow[mt] + kA);
            ldsm_x4(b01, stb + bRow0 + kB);
            ldsm_x4(b23, stb + bRow1 + kB);
            #pragma unroll
            for (int mt = 0; mt < 4; mt++) {
                mma_tf32(acc[mt][0], a[mt], b01);
                mma_tf32(acc[mt][1], a[mt], b01 + 2);
                mma_tf32(acc[mt][2], a[mt], b23);
                mma_tf32(acc[mt][3], a[mt], b23 + 2);
            }
        }
    }

    #pragma unroll
    for (int mt = 0; mt < 4; mt++) {
        const int r0 = bm + wm * 64 + mt * 16 + (lane >> 2);
        #pragma unroll
        for (int nt = 0; nt < 4; nt++) {
            const int col = bn + wn * 32 + nt * 8 + (lane & 3) * 2;
            const float bz0 = bias[col], bz1 = bias[col + 1];
            float c0 = acc[mt][nt][0] + bz0;
            float c1 = acc[mt][nt][1] + bz1;
            float c2 = acc[mt][nt][2] + bz0;
            float c3 = acc[mt][nt][3] + bz1;
            const size_t g0 = (size_t)r0 * N + col;
            const size_t g1 = (size_t)(r0 + 8) * N + col;
            if (MODE == 0) {
                c0 = round_tf32(c0 * normcdff(c0));
                c1 = round_tf32(c1 * normcdff(c1));
                c2 = round_tf32(c2 * normcdff(c2));
                c3 = round_tf32(c3 * normcdff(c3));
            } else {
                c0 += res[g0]; c1 += res[g0 + 1];
                c2 += res[g1]; c3 += res[g1 + 1];
            }
            float2 v0; v0.x = c0; v0.y = c1;
            float2 v1; v1.x = c2; v1.y = c3;
            *(float2*)&C[g0] = v0;
            *(float2*)&C[g1] = v1;
        }
    }
}

// ============================================================
extern "C" void kernel_launch(void* const* d_in, const int* in_sizes, int n_in,
                              void* d_out, int out_size)
{
    const float* input1 = (const float*)d_in[0];
    const float* Wv = (const float*)d_in[1];
    const float* bv = (const float*)d_in[2];
    const float* Wq = (const float*)d_in[3];
    const float* bq = (const float*)d_in[4];
    const float* Wk = (const float*)d_in[5];
    const float* bk = (const float*)d_in[6];
    const float* W1 = (const float*)d_in[7];
    const float* b1 = (const float*)d_in[8];
    const float* W2 = (const float*)d_in[9];
    const float* b2 = (const float*)d_in[10];
    float* out = (float*)d_out;

    float* s_Wt1; cudaGetSymbolAddress((void**)&s_Wt1, g_Wt1);
    float* s_Wt2; cudaGetSymbolAddress((void**)&s_Wt2, g_Wt2);

    cudaFuncSetAttribute(ln_proj_kernel, cudaFuncAttributeMaxDynamicSharedMemorySize, LN_SMEM_BYTES);
    cudaFuncSetAttribute(attn_kernel, cudaFuncAttributeMaxDynamicSharedMemorySize, ATT_SMEM_BYTES);
    cudaFuncSetAttribute(tc_gemm_kernel<0>, cudaFuncAttributeMaxDynamicSharedMemorySize, GEMM_SMEM_BYTES);
    cudaFuncSetAttribute(tc_gemm_kernel<1>, cudaFuncAttributeMaxDynamicSharedMemorySize, GEMM_SMEM_BYTES);

    transpose_round_kernel<<<dim3(FF / 32, E / 32), 256>>>(W1, s_Wt1, E, FF);
    transpose_round_kernel<<<dim3(E / 32, FF / 32), 256>>>(W2, s_Wt2, FF, E);

    ln_proj_kernel<<<NTOK / 32, 256, LN_SMEM_BYTES>>>(input1, Wv, bv, Wq, bq, Wk, bk);
    attn_kernel<<<dim3(S / 128, B * H), 256, ATT_SMEM_BYTES>>>();

    tc_gemm_kernel<0><<<dim3(FF / 128, NTOK / 128), 256, GEMM_SMEM_BYTES>>>(s_Wt1, b1, nullptr, nullptr, FF, E);
    tc_gemm_kernel<1><<<dim3(E / 128, NTOK / 128), 256, GEMM_SMEM_BYTES>>>(s_Wt2, b2, input1, out, E, FF);
}

// round 9
// speedup vs baseline: 2.3622x; 1.6159x over previous
#include <cuda_runtime.h>
#include <cuda_fp16.h>
#include <math.h>
#include <stdint.h>

#define B 4
#define S 2048
#define E 512
#define H 8
#define D 64
#define FF 2048
#define NTOK (B*S)

// ---- device scratch (static, allocation-free) ----
__device__ __half g_Vt[(size_t)B * H * D * S];   // V transposed: [b][h][d][s]
__device__ float  g_Q[(size_t)B * H * S];        // [b,h,s]
__device__ float  g_K[(size_t)B * H * S];        // [b,h,s]
__device__ __half g_HO[(size_t)NTOK * E];        // head_out [s][e]
__device__ __half g_MID[(size_t)NTOK * FF];      // GELU(h@W1+b1)
__device__ __half g_Wt1[(size_t)FF * E];         // W1^T [N=FF][K=E]
__device__ __half g_Wt2[(size_t)E * FF];         // W2^T [N=E][K=FF]

// ============================================================
// Helpers (arch-generic PTX: mma.sync / cp.async / ldmatrix)
// ============================================================
__device__ __forceinline__ uint32_t smem_u32(const void* p) {
    uint32_t a;
    asm("{ .reg .u64 t; cvta.to.shared.u64 t, %1; cvt.u32.u64 %0, t; }" : "=r"(a) : "l"(p));
    return a;
}
#define CP_ASYNC16(dst, src) \
    asm volatile("cp.async.cg.shared.global [%0], [%1], 16;" :: "r"(dst), "l"(src) : "memory")
#define CP_COMMIT() asm volatile("cp.async.commit_group;" ::: "memory")
template<int N> __device__ __forceinline__ void cp_wait() {
    asm volatile("cp.async.wait_group %0;" :: "n"(N) : "memory");
}
// m16n8k16 fp16 mma, fp32 accum
__device__ __forceinline__ void mma_f16(float* c, const uint32_t* a, const uint32_t* b) {
    asm volatile(
        "mma.sync.aligned.m16n8k16.row.col.f32.f16.f16.f32 "
        "{%0,%1,%2,%3}, {%4,%5,%6,%7}, {%8,%9}, {%0,%1,%2,%3};"
        : "+f"(c[0]), "+f"(c[1]), "+f"(c[2]), "+f"(c[3])
        : "r"(a[0]), "r"(a[1]), "r"(a[2]), "r"(a[3]), "r"(b[0]), "r"(b[1]));
}
__device__ __forceinline__ void ldsm_x4(uint32_t* r, uint32_t addr) {
    asm volatile("ldmatrix.sync.aligned.m8n8.x4.shared.b16 {%0,%1,%2,%3}, [%4];"
        : "=r"(r[0]), "=r"(r[1]), "=r"(r[2]), "=r"(r[3]) : "r"(addr));
}
__device__ __forceinline__ uint32_t pack_h2(float lo, float hi) {
    __half2 h = __floats2half2_rn(lo, hi);
    return *reinterpret_cast<uint32_t*>(&h);
}

// ============================================================
// Kernel 0: weight transpose + fp16 convert: W[K][N] -> Wt[N][K] (half)
// ============================================================
__global__ __launch_bounds__(256) void transpose_half_kernel(
    const float* __restrict__ W, __half* __restrict__ Wt, int K, int N)
{
    __shared__ float t[32][33];
    const int n0 = blockIdx.x * 32;
    const int k0 = blockIdx.y * 32;
    const int tx = threadIdx.x & 31;
    const int ty = threadIdx.x >> 5;
    #pragma unroll
    for (int r = 0; r < 4; r++)
        t[ty + r * 8][tx] = W[(size_t)(k0 + ty + r * 8) * N + n0 + tx];
    __syncthreads();
    #pragma unroll
    for (int r = 0; r < 4; r++)
        Wt[(size_t)(n0 + ty + r * 8) * K + k0 + tx] = __float2half_rn(t[tx][ty + r * 8]);
}

// ============================================================
// Kernel 1: LayerNorm + projections, 32 tokens per CTA (R8 structure).
// V written directly to transposed layout g_Vt[b][h][d][s] as half
// (thread owns (h,d): its 32 token results are contiguous in s).
// ============================================================
#define LN_SMEM_BYTES (32 * 512 * 4)

__global__ __launch_bounds__(256) void ln_proj_kernel(
    const float* __restrict__ x,
    const float* __restrict__ Wv, const float* __restrict__ bv,
    const float* __restrict__ Wq, const float* __restrict__ bq,
    const float* __restrict__ Wk, const float* __restrict__ bk)
{
    extern __shared__ float smem[];
    float (*xn)[512] = (float(*)[512])smem;

    const int tb = blockIdx.x * 32;
    const int tid = threadIdx.x;
    const int lane = tid & 31, wid = tid >> 5;

    // ---- Phase 1: LN (each warp: 4 tokens) ----
    #pragma unroll
    for (int tt = 0; tt < 4; tt++) {
        const int t = wid * 4 + tt;
        const float* xin = x + (size_t)(tb + t) * E;
        float v[16];
        float s = 0.f, ss = 0.f;
        #pragma unroll
        for (int j = 0; j < 16; j++) {
            v[j] = xin[lane + j * 32];
            s += v[j];
            ss = fmaf(v[j], v[j], ss);
        }
        #pragma unroll
        for (int o = 16; o > 0; o >>= 1) {
            s  += __shfl_xor_sync(0xffffffffu, s, o);
            ss += __shfl_xor_sync(0xffffffffu, ss, o);
        }
        const float mean = s * (1.0f / E);
        const float var  = ss * (1.0f / E) - mean * mean;
        const float rstd = rsqrtf(var + 1e-5f);
        #pragma unroll
        for (int j = 0; j < 16; j++)
            xn[t][lane + j * 32] = (v[j] - mean) * rstd;
    }
    __syncthreads();

    const int bidx = tb >> 11;
    const int s0 = tb & (S - 1);

    // ---- Phase 2: V projection, 32 tokens per thread-column ----
    #pragma unroll
    for (int rep = 0; rep < 2; rep++) {
        const int e = tid + rep * 256;
        const int h = e >> 6, d = e & 63;
        const float* w = Wv + (size_t)h * D * D + d;  // stride D over i (coalesced)
        const float bvv = bv[e];
        float acc[32];
        #pragma unroll
        for (int t = 0; t < 32; t++) acc[t] = bvv;
        const float* xh = &xn[0][h * 64];
        #pragma unroll 4
        for (int i = 0; i < D; i++) {
            const float wi = w[i * D];
            #pragma unroll
            for (int t = 0; t < 32; t++)
                acc[t] = fmaf(xh[t * 512 + i], wi, acc[t]);
        }
        // store 32 contiguous halves to g_Vt[b][h][d][s0..s0+31]
        uint32_t hb[16];
        #pragma unroll
        for (int t = 0; t < 16; t++) hb[t] = pack_h2(acc[t * 2], acc[t * 2 + 1]);
        uint4* dst = (uint4*)(g_Vt + ((size_t)(bidx * H + h) * D + d) * S + s0);
        const uint4* srcv = (const uint4*)hb;
        #pragma unroll
        for (int i = 0; i < 4; i++) dst[i] = srcv[i];
    }

    // ---- Phase 3: Q/K (thread = token x head) ----
    {
        const int t = tid >> 3, h = tid & 7;
        const float* wq = Wq + h * D;
        const float* wk = Wk + h * D;
        const float* xh = xn[t] + h * 64;
        float accq = bq[h], acck = bk[h];
        #pragma unroll
        for (int i = 0; i < D; i++) {
            const float xv = xh[i];
            accq = fmaf(xv, wq[i], accq);
            acck = fmaf(xv, wk[i], acck);
        }
        g_Q[((size_t)bidx * H + h) * S + s0 + t] = accq;
        g_K[((size_t)bidx * H + h) * S + s0 + t] = acck;
    }
}

// ============================================================
// Kernel 2: attention, fp16 mma m16n8k16, register-resident P.
// CTA: one (b,h), 128 queries; 8 warps each own 16q x 64d.
// V tiles [64 d][64 k] half, 16B-XOR swizzled, B-frags via ldmatrix.
// smem: Ksh 8KB (float) | 2 x 8KB V buffers
// ============================================================
#define ATT_SMEM_BYTES (8192 + 2 * 8192)

__global__ __launch_bounds__(256) void attn_kernel()
{
    extern __shared__ float smem[];
    float* Ksh = smem;                       // 2048 floats
    const uint32_t sbase = smem_u32(smem);
    const uint32_t vtbuf = sbase + 8192;

    const int bh = blockIdx.y;
    const int q0 = blockIdx.x * 128;
    const int tid = threadIdx.x;
    const int lane = tid & 31, wid = tid >> 5;
    const int l7 = lane & 7;
    const int cl = lane & 3;

    for (int i = tid; i < S; i += 256) Ksh[i] = g_K[(size_t)bh * S + i];

    const int r0 = wid * 16 + (lane >> 2);
    const float q0v = g_Q[(size_t)bh * S + q0 + r0];
    const float q1v = g_Q[(size_t)bh * S + q0 + r0 + 8];

    const __half* Vg = g_Vt + (size_t)bh * D * S;   // [d][s]
    auto loadV = [&](int kc, int buf) {
        #pragma unroll
        for (int p = 0; p < 2; p++) {
            const int row = (tid >> 3) + p * 32;
            const int seg = tid & 7;
            const __half* src = Vg + (size_t)row * S + kc * 64 + seg * 8;
            const uint32_t dst = vtbuf + buf * 8192 +
                (uint32_t)(row * 128 + ((seg ^ (row & 7)) * 16));
            CP_ASYNC16(dst, src);
        }
    };

    // B-frag ldmatrix row bases (row & 7 == l7 for all)
    uint32_t vRow[4];
    #pragma unroll
    for (int ntp = 0; ntp < 4; ntp++)
        vRow[ntp] = (uint32_t)((ntp * 16 + ((lane >> 4) & 1) * 8 + l7) * 128);
    const int selV = (lane >> 3) & 1;

    loadV(0, 0);
    CP_COMMIT();

    float acc[8][4];
    #pragma unroll
    for (int j = 0; j < 8; j++)
        #pragma unroll
        for (int l = 0; l < 4; l++) acc[j][l] = 0.f;
    float den0 = 0.f, den1 = 0.f;

    const float cexp = -0.125f * 1.4426950408889634f;

    const int NCH = S / 64;
    for (int kc = 0; kc < NCH; kc++) {
        const int buf = kc & 1;
        cp_wait<0>();
        __syncthreads();
        if (kc + 1 < NCH) { loadV(kc + 1, buf ^ 1); CP_COMMIT(); }

        const uint32_t vb = vtbuf + buf * 8192;
        #pragma unroll
        for (int ks = 0; ks < 4; ks++) {
            const int kA = kc * 64 + ks * 16 + cl * 2;
            const float2 k01 = *(const float2*)&Ksh[kA];
            const float2 k89 = *(const float2*)&Ksh[kA + 8];
            float d;
            d = q0v - k01.x; const float w00 = exp2f(d * d * cexp);
            d = q0v - k01.y; const float w01 = exp2f(d * d * cexp);
            d = q0v - k89.x; const float w08 = exp2f(d * d * cexp);
            d = q0v - k89.y; const float w09 = exp2f(d * d * cexp);
            d = q1v - k01.x; const float w10 = exp2f(d * d * cexp);
            d = q1v - k01.y; const float w11 = exp2f(d * d * cexp);
            d = q1v - k89.x; const float w18 = exp2f(d * d * cexp);
            d = q1v - k89.y; const float w19 = exp2f(d * d * cexp);
            den0 += (w00 + w01) + (w08 + w09);
            den1 += (w10 + w11) + (w18 + w19);
            uint32_t a[4];
            a[0] = pack_h2(w00, w01);
            a[1] = pack_h2(w10, w11);
            a[2] = pack_h2(w08, w09);
            a[3] = pack_h2(w18, w19);
            const uint32_t sw = (uint32_t)(((ks * 2 + selV) ^ l7) * 16);
            #pragma unroll
            for (int ntp = 0; ntp < 4; ntp++) {
                uint32_t bb[4];
                ldsm_x4(bb, vb + vRow[ntp] + sw);
                mma_f16(acc[ntp * 2],     a, bb);
                mma_f16(acc[ntp * 2 + 1], a, bb + 2);
            }
        }
    }

    den0 += __shfl_xor_sync(0xffffffffu, den0, 1);
    den0 += __shfl_xor_sync(0xffffffffu, den0, 2);
    den1 += __shfl_xor_sync(0xffffffffu, den1, 1);
    den1 += __shfl_xor_sync(0xffffffffu, den1, 2);
    const float inv0 = 1.0f / den0;
    const float inv1 = 1.0f / den1;

    const int b = bh >> 3, h = bh & 7;
    #pragma unroll
    for (int nt = 0; nt < 8; nt++) {
        const int col = nt * 8 + cl * 2;
        const size_t t0 = ((size_t)b * S + q0 + r0) * E + h * D + col;
        const size_t t1 = ((size_t)b * S + q0 + r0 + 8) * E + h * D + col;
        __half2 o0 = __floats2half2_rn(acc[nt][0] * inv0, acc[nt][1] * inv0);
        __half2 o1 = __floats2half2_rn(acc[nt][2] * inv1, acc[nt][3] * inv1);
        *(__half2*)&g_HO[t0] = o0;
        *(__half2*)&g_HO[t1] = o1;
    }
}

// ============================================================
// Kernel 3/4: fp16 mma GEMM. 128x128 CTA tile, BK=64 halves (128B rows),
// 3-stage cp.async, 16B-XOR swizzle, warps 2(m)x4(n) = 64x32.
// MODE 0: C=g_MID (half), epilogue GELU(x+b1)
// MODE 1: C=out (float), epilogue x + b2 + input1
// ============================================================
#define GEMM_SMEM_BYTES (3 * 32768)

template<int MODE>
__global__ __launch_bounds__(256) void hgemm_kernel(
    const __half* __restrict__ Bt, const float* __restrict__ bias,
    const float* __restrict__ res, float* __restrict__ Cout,
    int N, int K)
{
    extern __shared__ float smem[];
    const __half* A = (MODE == 0) ? g_HO : g_MID;

    const int tid = threadIdx.x;
    const int lane = tid & 31, wid = tid >> 5;
    const int l7 = lane & 7;
    const int bm = blockIdx.y * 128;
    const int bn = blockIdx.x * 128;
    const int wm = wid >> 2;   // 0..1
    const int wn = wid & 3;    // 0..3
    const uint32_t sbase = smem_u32(smem);

    const int lr = tid >> 3;
    const int lg = tid & 7;

    auto load_tile = [&](int kc, int st) {
        #pragma unroll
        for (int p = 0; p < 4; p++) {
            const int r = lr + p * 32;
            const uint32_t dst = sbase + (uint32_t)(st * 32768 + r * 128 + ((lg ^ (r & 7)) * 16));
            CP_ASYNC16(dst, A + (size_t)(bm + r) * K + kc * 64 + lg * 8);
            CP_ASYNC16(dst + 16384u, Bt + (size_t)(bn + r) * K + kc * 64 + lg * 8);
        }
    };

    // fragment row bases (row & 7 == l7 for all)
    uint32_t aRow[4];
    #pragma unroll
    for (int mt = 0; mt < 4; mt++)
        aRow[mt] = (uint32_t)((wm * 64 + mt * 16 + ((lane >> 3) & 1) * 8 + l7) * 128);
    const int selA = (lane >> 4) & 1;
    uint32_t bRow[2];
    #pragma unroll
    for (int ntp = 0; ntp < 2; ntp++)
        bRow[ntp] = 16384u + (uint32_t)((wn * 32 + ntp * 16 + ((lane >> 4) & 1) * 8 + l7) * 128);
    const int selB = (lane >> 3) & 1;

    float acc[4][4][4];
    #pragma unroll
    for (int i = 0; i < 4; i++)
        #pragma unroll
        for (int j = 0; j < 4; j++)
            #pragma unroll
            for (int l = 0; l < 4; l++) acc[i][j][l] = 0.f;

    const int nc = K / 64;
    load_tile(0, 0); CP_COMMIT();
    load_tile(1, 1); CP_COMMIT();

    for (int kc = 0; kc < nc; kc++) {
        const int st = kc % 3;
        if (kc + 1 < nc) cp_wait<1>(); else cp_wait<0>();
        __syncthreads();
        if (kc + 2 < nc) { load_tile(kc + 2, (kc + 2) % 3); CP_COMMIT(); }

        const uint32_t stb = sbase + (uint32_t)(st * 32768);
        #pragma unroll
        for (int ks = 0; ks < 4; ks++) {
            const uint32_t swA = (uint32_t)(((ks * 2 + selA) ^ l7) * 16);
            const uint32_t swB = (uint32_t)(((ks * 2 + selB) ^ l7) * 16);
            uint32_t a[4][4], b01[4], b23[4];
            #pragma unroll
            for (int mt = 0; mt < 4; mt++) ldsm_x4(a[mt], stb + aRow[mt] + swA);
            ldsm_x4(b01, stb + bRow[0] + swB);
            ldsm_x4(b23, stb + bRow[1] + swB);
            #pragma unroll
            for (int mt = 0; mt < 4; mt++) {
                mma_f16(acc[mt][0], a[mt], b01);
                mma_f16(acc[mt][1], a[mt], b01 + 2);
                mma_f16(acc[mt][2], a[mt], b23);
                mma_f16(acc[mt][3], a[mt], b23 + 2);
            }
        }
    }

    // epilogue
    #pragma unroll
    for (int mt = 0; mt < 4; mt++) {
        const int r0 = bm + wm * 64 + mt * 16 + (lane >> 2);
        #pragma unroll
        for (int nt = 0; nt < 4; nt++) {
            const int col = bn + wn * 32 + nt * 8 + (lane & 3) * 2;
            const float bz0 = bias[col], bz1 = bias[col + 1];
            float c0 = acc[mt][nt][0] + bz0;
            float c1 = acc[mt][nt][1] + bz1;
            float c2 = acc[mt][nt][2] + bz0;
            float c3 = acc[mt][nt][3] + bz1;
            const size_t g0 = (size_t)r0 * N + col;
            const size_t g1 = (size_t)(r0 + 8) * N + col;
            if (MODE == 0) {
                c0 = c0 * normcdff(c0);
                c1 = c1 * normcdff(c1);
                c2 = c2 * normcdff(c2);
                c3 = c3 * normcdff(c3);
                *(__half2*)&g_MID[g0] = __floats2half2_rn(c0, c1);
                *(__half2*)&g_MID[g1] = __floats2half2_rn(c2, c3);
            } else {
                const float2 ra = *(const float2*)&res[g0];
                const float2 rb = *(const float2*)&res[g1];
                float2 v0; v0.x = c0 + ra.x; v0.y = c1 + ra.y;
                float2 v1; v1.x = c2 + rb.x; v1.y = c3 + rb.y;
                *(float2*)&Cout[g0] = v0;
                *(float2*)&Cout[g1] = v1;
            }
        }
    }
}

// ============================================================
extern "C" void kernel_launch(void* const* d_in, const int* in_sizes, int n_in,
                              void* d_out, int out_size)
{
    const float* input1 = (const float*)d_in[0];
    const float* Wv = (const float*)d_in[1];
    const float* bv = (const float*)d_in[2];
    const float* Wq = (const float*)d_in[3];
    const float* bq = (const float*)d_in[4];
    const float* Wk = (const float*)d_in[5];
    const float* bk = (const float*)d_in[6];
    const float* W1 = (const float*)d_in[7];
    const float* b1 = (const float*)d_in[8];
    const float* W2 = (const float*)d_in[9];
    const float* b2 = (const float*)d_in[10];
    float* out = (float*)d_out;

    __half* s_Wt1; cudaGetSymbolAddress((void**)&s_Wt1, g_Wt1);
    __half* s_Wt2; cudaGetSymbolAddress((void**)&s_Wt2, g_Wt2);

    cudaFuncSetAttribute(ln_proj_kernel, cudaFuncAttributeMaxDynamicSharedMemorySize, LN_SMEM_BYTES);
    cudaFuncSetAttribute(attn_kernel, cudaFuncAttributeMaxDynamicSharedMemorySize, ATT_SMEM_BYTES);
    cudaFuncSetAttribute(hgemm_kernel<0>, cudaFuncAttributeMaxDynamicSharedMemorySize, GEMM_SMEM_BYTES);
    cudaFuncSetAttribute(hgemm_kernel<1>, cudaFuncAttributeMaxDynamicSharedMemorySize, GEMM_SMEM_BYTES);

    transpose_half_kernel<<<dim3(FF / 32, E / 32), 256>>>(W1, s_Wt1, E, FF);
    transpose_half_kernel<<<dim3(E / 32, FF / 32), 256>>>(W2, s_Wt2, FF, E);

    ln_proj_kernel<<<NTOK / 32, 256, LN_SMEM_BYTES>>>(input1, Wv, bv, Wq, bq, Wk, bk);
    attn_kernel<<<dim3(S / 128, B * H), 256, ATT_SMEM_BYTES>>>();

    hgemm_kernel<0><<<dim3(FF / 128, NTOK / 128), 256, GEMM_SMEM_BYTES>>>(s_Wt1, b1, nullptr, nullptr, FF, E);
    hgemm_kernel<1><<<dim3(E / 128, NTOK / 128), 256, GEMM_SMEM_BYTES>>>(s_Wt2, b2, input1, out, E, FF);
}

// round 10
// speedup vs baseline: 2.5335x; 1.0725x over previous
#include <cuda_runtime.h>
#include <cuda_fp16.h>
#include <math.h>
#include <stdint.h>

#define B 4
#define S 2048
#define E 512
#define H 8
#define D 64
#define FF 2048
#define NTOK (B*S)

// ---- device scratch (static, allocation-free) ----
__device__ __half g_Vt[(size_t)B * H * D * S];   // V transposed: [b][h][d][s]
__device__ float  g_Q[(size_t)B * H * S];        // [b,h,s]
__device__ float  g_K[(size_t)B * H * S];        // [b,h,s]
__device__ __half g_HO[(size_t)NTOK * E];        // head_out [s][e]
__device__ __half g_MID[(size_t)NTOK * FF];      // GELU(h@W1+b1)
__device__ __half g_Wt1[(size_t)FF * E];         // W1^T [N=FF][K=E]
__device__ __half g_Wt2[(size_t)E * FF];         // W2^T [N=E][K=FF]

// ============================================================
// Helpers (arch-generic PTX: mma.sync / cp.async / ldmatrix)
// ============================================================
__device__ __forceinline__ uint32_t smem_u32(const void* p) {
    uint32_t a;
    asm("{ .reg .u64 t; cvta.to.shared.u64 t, %1; cvt.u32.u64 %0, t; }" : "=r"(a) : "l"(p));
    return a;
}
#define CP_ASYNC16(dst, src) \
    asm volatile("cp.async.cg.shared.global [%0], [%1], 16;" :: "r"(dst), "l"(src) : "memory")
#define CP_COMMIT() asm volatile("cp.async.commit_group;" ::: "memory")
template<int N> __device__ __forceinline__ void cp_wait() {
    asm volatile("cp.async.wait_group %0;" :: "n"(N) : "memory");
}
// m16n8k16 fp16 mma, fp32 accum
__device__ __forceinline__ void mma_f16(float* c, const uint32_t* a, const uint32_t* b) {
    asm volatile(
        "mma.sync.aligned.m16n8k16.row.col.f32.f16.f16.f32 "
        "{%0,%1,%2,%3}, {%4,%5,%6,%7}, {%8,%9}, {%0,%1,%2,%3};"
        : "+f"(c[0]), "+f"(c[1]), "+f"(c[2]), "+f"(c[3])
        : "r"(a[0]), "r"(a[1]), "r"(a[2]), "r"(a[3]), "r"(b[0]), "r"(b[1]));
}
__device__ __forceinline__ void ldsm_x4(uint32_t* r, uint32_t addr) {
    asm volatile("ldmatrix.sync.aligned.m8n8.x4.shared.b16 {%0,%1,%2,%3}, [%4];"
        : "=r"(r[0]), "=r"(r[1]), "=r"(r[2]), "=r"(r[3]) : "r"(addr));
}
__device__ __forceinline__ uint32_t pack_h2(float lo, float hi) {
    __half2 h = __floats2half2_rn(lo, hi);
    return *reinterpret_cast<uint32_t*>(&h);
}

// ============================================================
// Kernel 0: weight transpose + fp16 convert: W[K][N] -> Wt[N][K] (half)
// ============================================================
__global__ __launch_bounds__(256) void transpose_half_kernel(
    const float* __restrict__ W, __half* __restrict__ Wt, int K, int N)
{
    __shared__ float t[32][33];
    const int n0 = blockIdx.x * 32;
    const int k0 = blockIdx.y * 32;
    const int tx = threadIdx.x & 31;
    const int ty = threadIdx.x >> 5;
    #pragma unroll
    for (int r = 0; r < 4; r++)
        t[ty + r * 8][tx] = W[(size_t)(k0 + ty + r * 8) * N + n0 + tx];
    __syncthreads();
    #pragma unroll
    for (int r = 0; r < 4; r++)
        Wt[(size_t)(n0 + ty + r * 8) * K + k0 + tx] = __float2half_rn(t[tx][ty + r * 8]);
}

// ============================================================
// Kernel 1: LayerNorm + projections, 32 tokens per CTA.
// Phase 2 x-reads vectorized to LDS.128 (i-quad inner step).
// ============================================================
#define LN_SMEM_BYTES (32 * 512 * 4)

__global__ __launch_bounds__(256) void ln_proj_kernel(
    const float* __restrict__ x,
    const float* __restrict__ Wv, const float* __restrict__ bv,
    const float* __restrict__ Wq, const float* __restrict__ bq,
    const float* __restrict__ Wk, const float* __restrict__ bk)
{
    extern __shared__ float smem[];
    float (*xn)[512] = (float(*)[512])smem;

    const int tb = blockIdx.x * 32;
    const int tid = threadIdx.x;
    const int lane = tid & 31, wid = tid >> 5;

    // ---- Phase 1: LN (each warp: 4 tokens) ----
    #pragma unroll
    for (int tt = 0; tt < 4; tt++) {
        const int t = wid * 4 + tt;
        const float* xin = x + (size_t)(tb + t) * E;
        float v[16];
        float s = 0.f, ss = 0.f;
        #pragma unroll
        for (int j = 0; j < 16; j++) {
            v[j] = xin[lane + j * 32];
            s += v[j];
            ss = fmaf(v[j], v[j], ss);
        }
        #pragma unroll
        for (int o = 16; o > 0; o >>= 1) {
            s  += __shfl_xor_sync(0xffffffffu, s, o);
            ss += __shfl_xor_sync(0xffffffffu, ss, o);
        }
        const float mean = s * (1.0f / E);
        const float var  = ss * (1.0f / E) - mean * mean;
        const float rstd = rsqrtf(var + 1e-5f);
        #pragma unroll
        for (int j = 0; j < 16; j++)
            xn[t][lane + j * 32] = (v[j] - mean) * rstd;
    }
    __syncthreads();

    const int bidx = tb >> 11;
    const int s0 = tb & (S - 1);

    // ---- Phase 2: V projection, 32 tokens per thread-column ----
    #pragma unroll
    for (int rep = 0; rep < 2; rep++) {
        const int e = tid + rep * 256;
        const int h = e >> 6, d = e & 63;
        const float* w = Wv + (size_t)h * D * D + d;  // stride D over i (coalesced)
        const float bvv = bv[e];
        float acc[32];
        #pragma unroll
        for (int t = 0; t < 32; t++) acc[t] = bvv;
        const float* xh = &xn[0][h * 64];
        #pragma unroll
        for (int i = 0; i < D; i += 4) {
            const float w0 = w[i * D];
            const float w1 = w[(i + 1) * D];
            const float w2 = w[(i + 2) * D];
            const float w3 = w[(i + 3) * D];
            #pragma unroll
            for (int t = 0; t < 32; t++) {
                const float4 xv = *(const float4*)&xh[t * 512 + i];
                float a0 = fmaf(xv.x, w0, acc[t]);
                float a1 = fmaf(xv.y, w1, a0);
                float a2 = fmaf(xv.z, w2, a1);
                acc[t] = fmaf(xv.w, w3, a2);
            }
        }
        // store 32 contiguous halves to g_Vt[b][h][d][s0..s0+31]
        uint32_t hb[16];
        #pragma unroll
        for (int t = 0; t < 16; t++) hb[t] = pack_h2(acc[t * 2], acc[t * 2 + 1]);
        uint4* dst = (uint4*)(g_Vt + ((size_t)(bidx * H + h) * D + d) * S + s0);
        const uint4* srcv = (const uint4*)hb;
        #pragma unroll
        for (int i = 0; i < 4; i++) dst[i] = srcv[i];
    }

    // ---- Phase 3: Q/K (thread = token x head) ----
    {
        const int t = tid >> 3, h = tid & 7;
        const float* wq = Wq + h * D;
        const float* wk = Wk + h * D;
        const float* xh = xn[t] + h * 64;
        float accq = bq[h], acck = bk[h];
        #pragma unroll
        for (int i = 0; i < D; i++) {
            const float xv = xh[i];
            accq = fmaf(xv, wq[i], accq);
            acck = fmaf(xv, wk[i], acck);
        }
        g_Q[((size_t)bidx * H + h) * S + s0 + t] = accq;
        g_K[((size_t)bidx * H + h) * S + s0 + t] = acck;
    }
}

// ============================================================
// Kernel 2: attention, fp16 mma, factored scores + ones-mma denominator.
// softmax(-(q-k)^2/8) == softmax(qk/4 - k^2/8)  (q^2 term cancels).
// Ksh2[i] = {k_i, -k_i^2*log2e/8}; per exp: 1 FFMA + 1 MUFU.
// den: extra mma with B=ones on the same packed A-frags (exact fp32
// row-sums, consistent with numerator; no shfl reduce needed).
// smem: Ksh2 16KB | 2 x 8KB V buffers
// ============================================================
#define ATT_SMEM_BYTES (16384 + 2 * 8192)

__global__ __launch_bounds__(256) void attn_kernel()
{
    extern __shared__ float smem[];
    float2* Ksh2 = (float2*)smem;            // 2048 x {k, bk}
    const uint32_t sbase = smem_u32(smem);
    const uint32_t vtbuf = sbase + 16384;

    const int bh = blockIdx.y;
    const int q0 = blockIdx.x * 128;
    const int tid = threadIdx.x;
    const int lane = tid & 31, wid = tid >> 5;
    const int l7 = lane & 7;
    const int cl = lane & 3;

    const float CB = -0.1803368801111204f;   // -log2e/8
    const float CQ =  0.7213475204444817f;   // log2e (qk/4 with q*... see below)
    // score*log2e = (qk/4 - k^2/8)*log2e = (q*log2e/4)*k + bk
    for (int i = tid; i < S; i += 256) {
        const float kv = g_K[(size_t)bh * S + i];
        float2 e2; e2.x = kv; e2.y = kv * kv * CB;
        Ksh2[i] = e2;
    }

    const int r0 = wid * 16 + (lane >> 2);
    const float qc0 = g_Q[(size_t)bh * S + q0 + r0] * (0.25f * CQ * 2.0f);       // q*log2e/4... see note
    const float qc1 = g_Q[(size_t)bh * S + q0 + r0 + 8] * (0.25f * CQ * 2.0f);
    // note: log2e = 1.4426950408889634; CQ*2 = 1.442695..., so qc = q*log2e/4.

    const __half* Vg = g_Vt + (size_t)bh * D * S;   // [d][s]
    auto loadV = [&](int kc, int buf) {
        #pragma unroll
        for (int p = 0; p < 2; p++) {
            const int row = (tid >> 3) + p * 32;
            const int seg = tid & 7;
            const __half* src = Vg + (size_t)row * S + kc * 64 + seg * 8;
            const uint32_t dst = vtbuf + buf * 8192 +
                (uint32_t)(row * 128 + ((seg ^ (row & 7)) * 16));
            CP_ASYNC16(dst, src);
        }
    };

    // B-frag ldmatrix row bases
    uint32_t vRow[4];
    #pragma unroll
    for (int ntp = 0; ntp < 4; ntp++)
        vRow[ntp] = (uint32_t)((ntp * 16 + ((lane >> 4) & 1) * 8 + l7) * 128);
    const int selV = (lane >> 3) & 1;

    loadV(0, 0);
    CP_COMMIT();

    float acc[8][4];
    #pragma unroll
    for (int j = 0; j < 8; j++)
        #pragma unroll
        for (int l = 0; l < 4; l++) acc[j][l] = 0.f;
    float accd[4] = {0.f, 0.f, 0.f, 0.f};
    const uint32_t ones[2] = { 0x3C003C00u, 0x3C003C00u };

    const int NCH = S / 64;
    for (int kc = 0; kc < NCH; kc++) {
        const int buf = kc & 1;
        cp_wait<0>();
        __syncthreads();
        if (kc + 1 < NCH) { loadV(kc + 1, buf ^ 1); CP_COMMIT(); }

        const uint32_t vb = vtbuf + buf * 8192;
        #pragma unroll
        for (int ks = 0; ks < 4; ks++) {
            const int kA = kc * 64 + ks * 16 + cl * 2;
            const float4 p01 = *(const float4*)&Ksh2[kA];       // {k0,b0,k1,b1}
            const float4 p89 = *(const float4*)&Ksh2[kA + 8];
            const float w00 = exp2f(fmaf(qc0, p01.x, p01.y));
            const float w01 = exp2f(fmaf(qc0, p01.z, p01.w));
            const float w08 = exp2f(fmaf(qc0, p89.x, p89.y));
            const float w09 = exp2f(fmaf(qc0, p89.z, p89.w));
            const float w10 = exp2f(fmaf(qc1, p01.x, p01.y));
            const float w11 = exp2f(fmaf(qc1, p01.z, p01.w));
            const float w18 = exp2f(fmaf(qc1, p89.x, p89.y));
            const float w19 = exp2f(fmaf(qc1, p89.z, p89.w));
            uint32_t a[4];
            a[0] = pack_h2(w00, w01);
            a[1] = pack_h2(w10, w11);
            a[2] = pack_h2(w08, w09);
            a[3] = pack_h2(w18, w19);
            mma_f16(accd, a, ones);          // denominator row-sums
            const uint32_t sw = (uint32_t)(((ks * 2 + selV) ^ l7) * 16);
            #pragma unroll
            for (int ntp = 0; ntp < 4; ntp++) {
                uint32_t bb[4];
                ldsm_x4(bb, vb + vRow[ntp] + sw);
                mma_f16(acc[ntp * 2],     a, bb);
                mma_f16(acc[ntp * 2 + 1], a, bb + 2);
            }
        }
    }

    const float inv0 = 1.0f / accd[0];
    const float inv1 = 1.0f / accd[2];

    const int b = bh >> 3, h = bh & 7;
    #pragma unroll
    for (int nt = 0; nt < 8; nt++) {
        const int col = nt * 8 + cl * 2;
        const size_t t0 = ((size_t)b * S + q0 + r0) * E + h * D + col;
        const size_t t1 = ((size_t)b * S + q0 + r0 + 8) * E + h * D + col;
        __half2 o0 = __floats2half2_rn(acc[nt][0] * inv0, acc[nt][1] * inv0);
        __half2 o1 = __floats2half2_rn(acc[nt][2] * inv1, acc[nt][3] * inv1);
        *(__half2*)&g_HO[t0] = o0;
        *(__half2*)&g_HO[t1] = o1;
    }
}

// ============================================================
// Kernel 3/4: fp16 mma GEMM (R9 version — keep).
// ============================================================
#define GEMM_SMEM_BYTES (3 * 32768)

template<int MODE>
__global__ __launch_bounds__(256) void hgemm_kernel(
    const __half* __restrict__ Bt, const float* __restrict__ bias,
    const float* __restrict__ res, float* __restrict__ Cout,
    int N, int K)
{
    extern __shared__ float smem[];
    const __half* A = (MODE == 0) ? g_HO : g_MID;

    const int tid = threadIdx.x;
    const int lane = tid & 31, wid = tid >> 5;
    const int l7 = lane & 7;
    const int bm = blockIdx.y * 128;
    const int bn = blockIdx.x * 128;
    const int wm = wid >> 2;
    const int wn = wid & 3;
    const uint32_t sbase = smem_u32(smem);

    const int lr = tid >> 3;
    const int lg = tid & 7;

    auto load_tile = [&](int kc, int st) {
        #pragma unroll
        for (int p = 0; p < 4; p++) {
            const int r = lr + p * 32;
            const uint32_t dst = sbase + (uint32_t)(st * 32768 + r * 128 + ((lg ^ (r & 7)) * 16));
            CP_ASYNC16(dst, A + (size_t)(bm + r) * K + kc * 64 + lg * 8);
            CP_ASYNC16(dst + 16384u, Bt + (size_t)(bn + r) * K + kc * 64 + lg * 8);
        }
    };

    uint32_t aRow[4];
    #pragma unroll
    for (int mt = 0; mt < 4; mt++)
        aRow[mt] = (uint32_t)((wm * 64 + mt * 16 + ((lane >> 3) & 1) * 8 + l7) * 128);
    const int selA = (lane >> 4) & 1;
    uint32_t bRow[2];
    #pragma unroll
    for (int ntp = 0; ntp < 2; ntp++)
        bRow[ntp] = 16384u + (uint32_t)((wn * 32 + ntp * 16 + ((lane >> 4) & 1) * 8 + l7) * 128);
    const int selB = (lane >> 3) & 1;

    float acc[4][4][4];
    #pragma unroll
    for (int i = 0; i < 4; i++)
        #pragma unroll
        for (int j = 0; j < 4; j++)
            #pragma unroll
            for (int l = 0; l < 4; l++) acc[i][j][l] = 0.f;

    const int nc = K / 64;
    load_tile(0, 0); CP_COMMIT();
    load_tile(1, 1); CP_COMMIT();

    for (int kc = 0; kc < nc; kc++) {
        const int st = kc % 3;
        if (kc + 1 < nc) cp_wait<1>(); else cp_wait<0>();
        __syncthreads();
        if (kc + 2 < nc) { load_tile(kc + 2, (kc + 2) % 3); CP_COMMIT(); }

        const uint32_t stb = sbase + (uint32_t)(st * 32768);
        #pragma unroll
        for (int ks = 0; ks < 4; ks++) {
            const uint32_t swA = (uint32_t)(((ks * 2 + selA) ^ l7) * 16);
            const uint32_t swB = (uint32_t)(((ks * 2 + selB) ^ l7) * 16);
            uint32_t a[4][4], b01[4], b23[4];
            #pragma unroll
            for (int mt = 0; mt < 4; mt++) ldsm_x4(a[mt], stb + aRow[mt] + swA);
            ldsm_x4(b01, stb + bRow[0] + swB);
            ldsm_x4(b23, stb + bRow[1] + swB);
            #pragma unroll
            for (int mt = 0; mt < 4; mt++) {
                mma_f16(acc[mt][0], a[mt], b01);
                mma_f16(acc[mt][1], a[mt], b01 + 2);
                mma_f16(acc[mt][2], a[mt], b23);
                mma_f16(acc[mt][3], a[mt], b23 + 2);
            }
        }
    }

    #pragma unroll
    for (int mt = 0; mt < 4; mt++) {
        const int r0 = bm + wm * 64 + mt * 16 + (lane >> 2);
        #pragma unroll
        for (int nt = 0; nt < 4; nt++) {
            const int col = bn + wn * 32 + nt * 8 + (lane & 3) * 2;
            const float bz0 = bias[col], bz1 = bias[col + 1];
            float c0 = acc[mt][nt][0] + bz0;
            float c1 = acc[mt][nt][1] + bz1;
            float c2 = acc[mt][nt][2] + bz0;
            float c3 = acc[mt][nt][3] + bz1;
            const size_t g0 = (size_t)r0 * N + col;
            const size_t g1 = (size_t)(r0 + 8) * N + col;
            if (MODE == 0) {
                c0 = c0 * normcdff(c0);
                c1 = c1 * normcdff(c1);
                c2 = c2 * normcdff(c2);
                c3 = c3 * normcdff(c3);
                *(__half2*)&g_MID[g0] = __floats2half2_rn(c0, c1);
                *(__half2*)&g_MID[g1] = __floats2half2_rn(c2, c3);
            } else {
                const float2 ra = *(const float2*)&res[g0];
                const float2 rb = *(const float2*)&res[g1];
                float2 v0; v0.x = c0 + ra.x; v0.y = c1 + ra.y;
                float2 v1; v1.x = c2 + rb.x; v1.y = c3 + rb.y;
                *(float2*)&Cout[g0] = v0;
                *(float2*)&Cout[g1] = v1;
            }
        }
    }
}

// ============================================================
extern "C" void kernel_launch(void* const* d_in, const int* in_sizes, int n_in,
                              void* d_out, int out_size)
{
    const float* input1 = (const float*)d_in[0];
    const float* Wv = (const float*)d_in[1];
    const float* bv = (const float*)d_in[2];
    const float* Wq = (const float*)d_in[3];
    const float* bq = (const float*)d_in[4];
    const float* Wk = (const float*)d_in[5];
    const float* bk = (const float*)d_in[6];
    const float* W1 = (const float*)d_in[7];
    const float* b1 = (const float*)d_in[8];
    const float* W2 = (const float*)d_in[9];
    const float* b2 = (const float*)d_in[10];
    float* out = (float*)d_out;

    __half* s_Wt1; cudaGetSymbolAddress((void**)&s_Wt1, g_Wt1);
    __half* s_Wt2; cudaGetSymbolAddress((void**)&s_Wt2, g_Wt2);

    cudaFuncSetAttribute(ln_proj_kernel, cudaFuncAttributeMaxDynamicSharedMemorySize, LN_SMEM_BYTES);
    cudaFuncSetAttribute(attn_kernel, cudaFuncAttributeMaxDynamicSharedMemorySize, ATT_SMEM_BYTES);
    cudaFuncSetAttribute(hgemm_kernel<0>, cudaFuncAttributeMaxDynamicSharedMemorySize, GEMM_SMEM_BYTES);
    cudaFuncSetAttribute(hgemm_kernel<1>, cudaFuncAttributeMaxDynamicSharedMemorySize, GEMM_SMEM_BYTES);

    transpose_half_kernel<<<dim3(FF / 32, E / 32), 256>>>(W1, s_Wt1, E, FF);
    transpose_half_kernel<<<dim3(E / 32, FF / 32), 256>>>(W2, s_Wt2, FF, E);

    ln_proj_kernel<<<NTOK / 32, 256, LN_SMEM_BYTES>>>(input1, Wv, bv, Wq, bq, Wk, bk);
    attn_kernel<<<dim3(S / 128, B * H), 256, ATT_SMEM_BYTES>>>();

    hgemm_kernel<0><<<dim3(FF / 128, NTOK / 128), 256, GEMM_SMEM_BYTES>>>(s_Wt1, b1, nullptr, nullptr, FF, E);
    hgemm_kernel<1><<<dim3(E / 128, NTOK / 128), 256, GEMM_SMEM_BYTES>>>(s_Wt2, b2, input1, out, E, FF);
}

// round 11
// speedup vs baseline: 2.6098x; 1.0301x over previous
#include <cuda_runtime.h>
#include <cuda_fp16.h>
#include <math.h>
#include <stdint.h>

#define B 4
#define S 2048
#define E 512
#define H 8
#define D 64
#define FF 2048
#define NTOK (B*S)

// ---- device scratch (static, allocation-free) ----
__device__ __half g_Vt[(size_t)B * H * D * S];   // V transposed: [b][h][d][s]
__device__ float  g_Q[(size_t)B * H * S];        // [b,h,s]
__device__ float  g_K[(size_t)B * H * S];        // [b,h,s]
__device__ __half g_HO[(size_t)NTOK * E];        // head_out [s][e]
__device__ __half g_MID[(size_t)NTOK * FF];      // GELU(h@W1+b1)
__device__ __half g_Wt1[(size_t)FF * E];         // W1^T [N=FF][K=E]
__device__ __half g_Wt2[(size_t)E * FF];         // W2^T [N=E][K=FF]

// ============================================================
// Helpers (arch-generic PTX: mma.sync / cp.async / ldmatrix / ex2.f16x2)
// ============================================================
__device__ __forceinline__ uint32_t smem_u32(const void* p) {
    uint32_t a;
    asm("{ .reg .u64 t; cvta.to.shared.u64 t, %1; cvt.u32.u64 %0, t; }" : "=r"(a) : "l"(p));
    return a;
}
#define CP_ASYNC16(dst, src) \
    asm volatile("cp.async.cg.shared.global [%0], [%1], 16;" :: "r"(dst), "l"(src) : "memory")
#define CP_COMMIT() asm volatile("cp.async.commit_group;" ::: "memory")
template<int N> __device__ __forceinline__ void cp_wait() {
    asm volatile("cp.async.wait_group %0;" :: "n"(N) : "memory");
}
// m16n8k16 fp16 mma, fp32 accum
__device__ __forceinline__ void mma_f16(float* c, const uint32_t* a, const uint32_t* b) {
    asm volatile(
        "mma.sync.aligned.m16n8k16.row.col.f32.f16.f16.f32 "
        "{%0,%1,%2,%3}, {%4,%5,%6,%7}, {%8,%9}, {%0,%1,%2,%3};"
        : "+f"(c[0]), "+f"(c[1]), "+f"(c[2]), "+f"(c[3])
        : "r"(a[0]), "r"(a[1]), "r"(a[2]), "r"(a[3]), "r"(b[0]), "r"(b[1]));
}
__device__ __forceinline__ void ldsm_x4(uint32_t* r, uint32_t addr) {
    asm volatile("ldmatrix.sync.aligned.m8n8.x4.shared.b16 {%0,%1,%2,%3}, [%4];"
        : "=r"(r[0]), "=r"(r[1]), "=r"(r[2]), "=r"(r[3]) : "r"(addr));
}
__device__ __forceinline__ uint32_t pack_h2(float lo, float hi) {
    __half2 h = __floats2half2_rn(lo, hi);
    return *reinterpret_cast<uint32_t*>(&h);
}
__device__ __forceinline__ __half2 u2h2(uint32_t u) {
    return *reinterpret_cast<__half2*>(&u);
}
__device__ __forceinline__ uint32_t h22u(__half2 h) {
    return *reinterpret_cast<uint32_t*>(&h);
}

// ============================================================
// Kernel 0: weight transpose + fp16 convert: W[K][N] -> Wt[N][K] (half)
// ============================================================
__global__ __launch_bounds__(256) void transpose_half_kernel(
    const float* __restrict__ W, __half* __restrict__ Wt, int K, int N)
{
    __shared__ float t[32][33];
    const int n0 = blockIdx.x * 32;
    const int k0 = blockIdx.y * 32;
    const int tx = threadIdx.x & 31;
    const int ty = threadIdx.x >> 5;
    #pragma unroll
    for (int r = 0; r < 4; r++)
        t[ty + r * 8][tx] = W[(size_t)(k0 + ty + r * 8) * N + n0 + tx];
    __syncthreads();
    #pragma unroll
    for (int r = 0; r < 4; r++)
        Wt[(size_t)(n0 + ty + r * 8) * K + k0 + tx] = __float2half_rn(t[tx][ty + r * 8]);
}

// ============================================================
// Kernel 1: LayerNorm + projections, 32 tokens per CTA.
// ============================================================
#define LN_SMEM_BYTES (32 * 512 * 4)

__global__ __launch_bounds__(256) void ln_proj_kernel(
    const float* __restrict__ x,
    const float* __restrict__ Wv, const float* __restrict__ bv,
    const float* __restrict__ Wq, const float* __restrict__ bq,
    const float* __restrict__ Wk, const float* __restrict__ bk)
{
    extern __shared__ float smem[];
    float (*xn)[512] = (float(*)[512])smem;

    const int tb = blockIdx.x * 32;
    const int tid = threadIdx.x;
    const int lane = tid & 31, wid = tid >> 5;

    // ---- Phase 1: LN (each warp: 4 tokens) ----
    #pragma unroll
    for (int tt = 0; tt < 4; tt++) {
        const int t = wid * 4 + tt;
        const float* xin = x + (size_t)(tb + t) * E;
        float v[16];
        float s = 0.f, ss = 0.f;
        #pragma unroll
        for (int j = 0; j < 16; j++) {
            v[j] = xin[lane + j * 32];
            s += v[j];
            ss = fmaf(v[j], v[j], ss);
        }
        #pragma unroll
        for (int o = 16; o > 0; o >>= 1) {
            s  += __shfl_xor_sync(0xffffffffu, s, o);
            ss += __shfl_xor_sync(0xffffffffu, ss, o);
        }
        const float mean = s * (1.0f / E);
        const float var  = ss * (1.0f / E) - mean * mean;
        const float rstd = rsqrtf(var + 1e-5f);
        #pragma unroll
        for (int j = 0; j < 16; j++)
            xn[t][lane + j * 32] = (v[j] - mean) * rstd;
    }
    __syncthreads();

    const int bidx = tb >> 11;
    const int s0 = tb & (S - 1);

    // ---- Phase 2: V projection, 32 tokens per thread-column ----
    #pragma unroll
    for (int rep = 0; rep < 2; rep++) {
        const int e = tid + rep * 256;
        const int h = e >> 6, d = e & 63;
        const float* w = Wv + (size_t)h * D * D + d;  // stride D over i (coalesced)
        const float bvv = bv[e];
        float acc[32];
        #pragma unroll
        for (int t = 0; t < 32; t++) acc[t] = bvv;
        const float* xh = &xn[0][h * 64];
        #pragma unroll
        for (int i = 0; i < D; i += 4) {
            const float w0 = w[i * D];
            const float w1 = w[(i + 1) * D];
            const float w2 = w[(i + 2) * D];
            const float w3 = w[(i + 3) * D];
            #pragma unroll
            for (int t = 0; t < 32; t++) {
                const float4 xv = *(const float4*)&xh[t * 512 + i];
                float a0 = fmaf(xv.x, w0, acc[t]);
                float a1 = fmaf(xv.y, w1, a0);
                float a2 = fmaf(xv.z, w2, a1);
                acc[t] = fmaf(xv.w, w3, a2);
            }
        }
        uint32_t hb[16];
        #pragma unroll
        for (int t = 0; t < 16; t++) hb[t] = pack_h2(acc[t * 2], acc[t * 2 + 1]);
        uint4* dst = (uint4*)(g_Vt + ((size_t)(bidx * H + h) * D + d) * S + s0);
        const uint4* srcv = (const uint4*)hb;
        #pragma unroll
        for (int i = 0; i < 4; i++) dst[i] = srcv[i];
    }

    // ---- Phase 3: Q/K (thread = token x head) ----
    {
        const int t = tid >> 3, h = tid & 7;
        const float* wq = Wq + h * D;
        const float* wk = Wk + h * D;
        const float* xh = xn[t] + h * 64;
        float accq = bq[h], acck = bk[h];
        #pragma unroll
        for (int i = 0; i < D; i++) {
            const float xv = xh[i];
            accq = fmaf(xv, wq[i], accq);
            acck = fmaf(xv, wk[i], acck);
        }
        g_Q[((size_t)bidx * H + h) * S + s0 + t] = accq;
        g_K[((size_t)bidx * H + h) * S + s0 + t] = acck;
    }
}

// ============================================================
// Kernel 2: attention, fp16 mma, half2 exponentials.
// softmax(-(q-k)^2/8) == softmax(qk/4 - k^2/8)  (q^2 cancels).
// K staged as pair-packed half2 arrays: KK[j] = {kk2(j), kb2(j)} uint2,
// kk2 = {k_2j, k_2j+1}, kb2 = {-k^2*log2e/8 pair}.
// Per ks-step: 2 LDS.64 + 4 HFMA2 + 4 ex2.f16x2 + 4 LDSM + 9 HMMA.
// den via ones-MMA on the same A-frags.
// smem: KK 8KB | 2 x 8KB V buffers
// ============================================================
#define ATT_SMEM_BYTES (8192 + 2 * 8192)

__global__ __launch_bounds__(256) void attn_kernel()
{
    extern __shared__ float smem[];
    uint2* KK = (uint2*)smem;                // 1024 pairs
    const uint32_t sbase = smem_u32(smem);
    const uint32_t vtbuf = sbase + 8192;

    const int bh = blockIdx.y;
    const int q0 = blockIdx.x * 128;
    const int tid = threadIdx.x;
    const int lane = tid & 31, wid = tid >> 5;
    const int l7 = lane & 7;
    const int cl = lane & 3;

    const float CB = -0.1803368801111204f;   // -log2e/8
    const float CQ =  0.3606737602222409f;   // log2e/4
    for (int j = tid; j < S / 2; j += 256) {
        const float2 kv = *(const float2*)&g_K[(size_t)bh * S + 2 * j];
        uint2 e;
        e.x = pack_h2(kv.x, kv.y);
        e.y = pack_h2(kv.x * kv.x * CB, kv.y * kv.y * CB);
        KK[j] = e;
    }

    const int r0 = wid * 16 + (lane >> 2);
    const float qc0 = g_Q[(size_t)bh * S + q0 + r0] * CQ;
    const float qc1 = g_Q[(size_t)bh * S + q0 + r0 + 8] * CQ;
    const __half2 qc0h = __floats2half2_rn(qc0, qc0);
    const __half2 qc1h = __floats2half2_rn(qc1, qc1);

    const __half* Vg = g_Vt + (size_t)bh * D * S;   // [d][s]
    auto loadV = [&](int kc, int buf) {
        #pragma unroll
        for (int p = 0; p < 2; p++) {
            const int row = (tid >> 3) + p * 32;
            const int seg = tid & 7;
            const __half* src = Vg + (size_t)row * S + kc * 64 + seg * 8;
            const uint32_t dst = vtbuf + buf * 8192 +
                (uint32_t)(row * 128 + ((seg ^ (row & 7)) * 16));
            CP_ASYNC16(dst, src);
        }
    };

    // B-frag ldmatrix row bases
    uint32_t vRow[4];
    #pragma unroll
    for (int ntp = 0; ntp < 4; ntp++)
        vRow[ntp] = (uint32_t)((ntp * 16 + ((lane >> 4) & 1) * 8 + l7) * 128);
    const int selV = (lane >> 3) & 1;

    loadV(0, 0);
    CP_COMMIT();

    float acc[8][4];
    #pragma unroll
    for (int j = 0; j < 8; j++)
        #pragma unroll
        for (int l = 0; l < 4; l++) acc[j][l] = 0.f;
    float accd[4] = {0.f, 0.f, 0.f, 0.f};
    const uint32_t ones[2] = { 0x3C003C00u, 0x3C003C00u };

    const int NCH = S / 64;
    for (int kc = 0; kc < NCH; kc++) {
        const int buf = kc & 1;
        cp_wait<0>();
        __syncthreads();
        if (kc + 1 < NCH) { loadV(kc + 1, buf ^ 1); CP_COMMIT(); }

        const uint32_t vb = vtbuf + buf * 8192;
        #pragma unroll
        for (int ks = 0; ks < 4; ks++) {
            const int jb = kc * 32 + ks * 8;
            const uint2 e0 = KK[jb + cl];
            const uint2 e1 = KK[jb + cl + 4];
            uint32_t a[4];
            a[0] = h22u(h2exp2(__hfma2(qc0h, u2h2(e0.x), u2h2(e0.y))));
            a[1] = h22u(h2exp2(__hfma2(qc1h, u2h2(e0.x), u2h2(e0.y))));
            a[2] = h22u(h2exp2(__hfma2(qc0h, u2h2(e1.x), u2h2(e1.y))));
            a[3] = h22u(h2exp2(__hfma2(qc1h, u2h2(e1.x), u2h2(e1.y))));
            mma_f16(accd, a, ones);          // denominator row-sums
            const uint32_t sw = (uint32_t)(((ks * 2 + selV) ^ l7) * 16);
            #pragma unroll
            for (int ntp = 0; ntp < 4; ntp++) {
                uint32_t bb[4];
                ldsm_x4(bb, vb + vRow[ntp] + sw);
                mma_f16(acc[ntp * 2],     a, bb);
                mma_f16(acc[ntp * 2 + 1], a, bb + 2);
            }
        }
    }

    const float inv0 = 1.0f / accd[0];
    const float inv1 = 1.0f / accd[2];

    const int b = bh >> 3, h = bh & 7;
    #pragma unroll
    for (int nt = 0; nt < 8; nt++) {
        const int col = nt * 8 + cl * 2;
        const size_t t0 = ((size_t)b * S + q0 + r0) * E + h * D + col;
        const size_t t1 = ((size_t)b * S + q0 + r0 + 8) * E + h * D + col;
        __half2 o0 = __floats2half2_rn(acc[nt][0] * inv0, acc[nt][1] * inv0);
        __half2 o1 = __floats2half2_rn(acc[nt][2] * inv1, acc[nt][3] * inv1);
        *(__half2*)&g_HO[t0] = o0;
        *(__half2*)&g_HO[t1] = o1;
    }
}

// ============================================================
// Kernel 3/4: fp16 mma GEMM (unchanged — best-known config).
// ============================================================
#define GEMM_SMEM_BYTES (3 * 32768)

template<int MODE>
__global__ __launch_bounds__(256) void hgemm_kernel(
    const __half* __restrict__ Bt, const float* __restrict__ bias,
    const float* __restrict__ res, float* __restrict__ Cout,
    int N, int K)
{
    extern __shared__ float smem[];
    const __half* A = (MODE == 0) ? g_HO : g_MID;

    const int tid = threadIdx.x;
    const int lane = tid & 31, wid = tid >> 5;
    const int l7 = lane & 7;
    const int bm = blockIdx.y * 128;
    const int bn = blockIdx.x * 128;
    const int wm = wid >> 2;
    const int wn = wid & 3;
    const uint32_t sbase = smem_u32(smem);

    const int lr = tid >> 3;
    const int lg = tid & 7;

    auto load_tile = [&](int kc, int st) {
        #pragma unroll
        for (int p = 0; p < 4; p++) {
            const int r = lr + p * 32;
            const uint32_t dst = sbase + (uint32_t)(st * 32768 + r * 128 + ((lg ^ (r & 7)) * 16));
            CP_ASYNC16(dst, A + (size_t)(bm + r) * K + kc * 64 + lg * 8);
            CP_ASYNC16(dst + 16384u, Bt + (size_t)(bn + r) * K + kc * 64 + lg * 8);
        }
    };

    uint32_t aRow[4];
    #pragma unroll
    for (int mt = 0; mt < 4; mt++)
        aRow[mt] = (uint32_t)((wm * 64 + mt * 16 + ((lane >> 3) & 1) * 8 + l7) * 128);
    const int selA = (lane >> 4) & 1;
    uint32_t bRow[2];
    #pragma unroll
    for (int ntp = 0; ntp < 2; ntp++)
        bRow[ntp] = 16384u + (uint32_t)((wn * 32 + ntp * 16 + ((lane >> 4) & 1) * 8 + l7) * 128);
    const int selB = (lane >> 3) & 1;

    float acc[4][4][4];
    #pragma unroll
    for (int i = 0; i < 4; i++)
        #pragma unroll
        for (int j = 0; j < 4; j++)
            #pragma unroll
            for (int l = 0; l < 4; l++) acc[i][j][l] = 0.f;

    const int nc = K / 64;
    load_tile(0, 0); CP_COMMIT();
    load_tile(1, 1); CP_COMMIT();

    for (int kc = 0; kc < nc; kc++) {
        const int st = kc % 3;
        if (kc + 1 < nc) cp_wait<1>(); else cp_wait<0>();
        __syncthreads();
        if (kc + 2 < nc) { load_tile(kc + 2, (kc + 2) % 3); CP_COMMIT(); }

        const uint32_t stb = sbase + (uint32_t)(st * 32768);
        #pragma unroll
        for (int ks = 0; ks < 4; ks++) {
            const uint32_t swA = (uint32_t)(((ks * 2 + selA) ^ l7) * 16);
            const uint32_t swB = (uint32_t)(((ks * 2 + selB) ^ l7) * 16);
            uint32_t a[4][4], b01[4], b23[4];
            #pragma unroll
            for (int mt = 0; mt < 4; mt++) ldsm_x4(a[mt], stb + aRow[mt] + swA);
            ldsm_x4(b01, stb + bRow[0] + swB);
            ldsm_x4(b23, stb + bRow[1] + swB);
            #pragma unroll
            for (int mt = 0; mt < 4; mt++) {
                mma_f16(acc[mt][0], a[mt], b01);
                mma_f16(acc[mt][1], a[mt], b01 + 2);
                mma_f16(acc[mt][2], a[mt], b23);
                mma_f16(acc[mt][3], a[mt], b23 + 2);
            }
        }
    }

    #pragma unroll
    for (int mt = 0; mt < 4; mt++) {
        const int r0 = bm + wm * 64 + mt * 16 + (lane >> 2);
        #pragma unroll
        for (int nt = 0; nt < 4; nt++) {
            const int col = bn + wn * 32 + nt * 8 + (lane & 3) * 2;
            const float bz0 = bias[col], bz1 = bias[col + 1];
            float c0 = acc[mt][nt][0] + bz0;
            float c1 = acc[mt][nt][1] + bz1;
            float c2 = acc[mt][nt][2] + bz0;
            float c3 = acc[mt][nt][3] + bz1;
            const size_t g0 = (size_t)r0 * N + col;
            const size_t g1 = (size_t)(r0 + 8) * N + col;
            if (MODE == 0) {
                c0 = c0 * normcdff(c0);
                c1 = c1 * normcdff(c1);
                c2 = c2 * normcdff(c2);
                c3 = c3 * normcdff(c3);
                *(__half2*)&g_MID[g0] = __floats2half2_rn(c0, c1);
                *(__half2*)&g_MID[g1] = __floats2half2_rn(c2, c3);
            } else {
                const float2 ra = *(const float2*)&res[g0];
                const float2 rb = *(const float2*)&res[g1];
                float2 v0; v0.x = c0 + ra.x; v0.y = c1 + ra.y;
                float2 v1; v1.x = c2 + rb.x; v1.y = c3 + rb.y;
                *(float2*)&Cout[g0] = v0;
                *(float2*)&Cout[g1] = v1;
            }
        }
    }
}

// ============================================================
extern "C" void kernel_launch(void* const* d_in, const int* in_sizes, int n_in,
                              void* d_out, int out_size)
{
    const float* input1 = (const float*)d_in[0];
    const float* Wv = (const float*)d_in[1];
    const float* bv = (const float*)d_in[2];
    const float* Wq = (const float*)d_in[3];
    const float* bq = (const float*)d_in[4];
    const float* Wk = (const float*)d_in[5];
    const float* bk = (const float*)d_in[6];
    const float* W1 = (const float*)d_in[7];
    const float* b1 = (const float*)d_in[8];
    const float* W2 = (const float*)d_in[9];
    const float* b2 = (const float*)d_in[10];
    float* out = (float*)d_out;

    __half* s_Wt1; cudaGetSymbolAddress((void**)&s_Wt1, g_Wt1);
    __half* s_Wt2; cudaGetSymbolAddress((void**)&s_Wt2, g_Wt2);

    cudaFuncSetAttribute(ln_proj_kernel, cudaFuncAttributeMaxDynamicSharedMemorySize, LN_SMEM_BYTES);
    cudaFuncSetAttribute(attn_kernel, cudaFuncAttributeMaxDynamicSharedMemorySize, ATT_SMEM_BYTES);
    cudaFuncSetAttribute(hgemm_kernel<0>, cudaFuncAttributeMaxDynamicSharedMemorySize, GEMM_SMEM_BYTES);
    cudaFuncSetAttribute(hgemm_kernel<1>, cudaFuncAttributeMaxDynamicSharedMemorySize, GEMM_SMEM_BYTES);

    transpose_half_kernel<<<dim3(FF / 32, E / 32), 256>>>(W1, s_Wt1, E, FF);
    transpose_half_kernel<<<dim3(E / 32, FF / 32), 256>>>(W2, s_Wt2, FF, E);

    ln_proj_kernel<<<NTOK / 32, 256, LN_SMEM_BYTES>>>(input1, Wv, bv, Wq, bq, Wk, bk);
    attn_kernel<<<dim3(S / 128, B * H), 256, ATT_SMEM_BYTES>>>();

    hgemm_kernel<0><<<dim3(FF / 128, NTOK / 128), 256, GEMM_SMEM_BYTES>>>(s_Wt1, b1, nullptr, nullptr, FF, E);
    hgemm_kernel<1><<<dim3(E / 128, NTOK / 128), 256, GEMM_SMEM_BYTES>>>(s_Wt2, b2, input1, out, E, FF);
}